// round 10
// baseline (speedup 1.0000x reference)
#include <cuda_runtime.h>
#include <cuda_bf16.h>
#include <cstdint>
#include <math.h>

__device__ float g_c1[48*256*900];
__device__ float g_xe[48*256*900];
__device__ float g_xd[48*256*900];
__device__ float g_q [48*900*256];
__device__ float g_k [48*900*256];
__device__ float g_v [48*900*256];
__device__ float g_z [900*8*48*48];
__device__ float g_cmax[8*48*48];
__device__ float g_csum[8*48*48];
__device__ float g_ao[48*900*256];
__device__ float g_t1[48*900*256];
__device__ float g_t2[48*900*256];
__device__ float g_t3[48*900*256];
__device__ float g_ff[48*900*1024];
__device__ float g_y [48*900];
__device__ __nv_bfloat16 g_ah[99532800u];
__device__ __nv_bfloat16 g_al[99532800u];
__device__ __nv_bfloat16 g_bh[2359296u];
__device__ __nv_bfloat16 g_bl[2359296u];

__global__ void mma_gemm_k(const __nv_bfloat16* Ah, const __nv_bfloat16* Al,
                           const __nv_bfloat16* Bh, const __nv_bfloat16* Bl,
                           const float* bias, float* C, int M, int N, int K, int mode);
__global__ void split_act_k(const float* x, __nv_bfloat16* hi, __nv_bfloat16* lo, unsigned n);
__global__ void split_w_k(const float* w, __nv_bfloat16* hi, __nv_bfloat16* lo, int N, int K, int Kp);
__global__ void im2col1_k(const float* X, __nv_bfloat16* hi, __nv_bfloat16* lo);
__global__ void im2col2_k(const float* in, __nv_bfloat16* hi, __nv_bfloat16* lo);
__global__ void attn_scores_k(const float* Q, const float* Kb, const float* RW, float* Z);
__global__ void attn_scores_masked_k(const float* Q, const float* Kb, const float* RW,
                                     const float* L1w, const float* L1b,
                                     const float* L2w, const float* L2b, float* Z);
__global__ void col_max_k(const float* Z, float* cmax);
__global__ void col_expsum_k(float* Z, const float* cmax, float* csum);
__global__ void attn_out_k(const float* Z, const float* csum, const float* V, float* O);
__global__ void add_ln_k(const float* A, const float* B, float* O);
__global__ void outproj_k(const float* H, const float* w, const float* b, float* y);
__global__ void final_softmax_k(const float* y, float* out);

extern "C" void kernel_launch(void* const* d_in, const int* in_sizes, int n_in,
                              void* d_out, int out_size)
{
    const float* X_en = (const float*)d_in[0];
    const float* X_de = (const float*)d_in[1];
    const float* c1w = (const float*)d_in[2];
    const float* c1b = (const float*)d_in[3];
    const float* c2w = (const float*)d_in[4];
    const float* c2b = (const float*)d_in[5];
    const float* enc_wq = (const float*)d_in[6];
    const float* enc_wk = (const float*)d_in[7];
    const float* enc_wv = (const float*)d_in[8];
    const float* enc_rel = (const float*)d_in[9];
    const float* e_w1 = (const float*)d_in[10];
    const float* e_b1 = (const float*)d_in[11];
    const float* e_w2 = (const float*)d_in[12];
    const float* e_b2 = (const float*)d_in[13];
    const float* m_wq = (const float*)d_in[14];
    const float* m_wk = (const float*)d_in[15];
    const float* m_wv = (const float*)d_in[16];
    const float* m_rel = (const float*)d_in[17];
    const float* l1w = (const float*)d_in[18];
    const float* l1b = (const float*)d_in[19];
    const float* l2w = (const float*)d_in[20];
    const float* l2b = (const float*)d_in[21];
    const float* c_wq = (const float*)d_in[22];
    const float* c_wk = (const float*)d_in[23];
    const float* c_wv = (const float*)d_in[24];
    const float* c_rel = (const float*)d_in[25];
    const float* d_w1 = (const float*)d_in[26];
    const float* d_b1 = (const float*)d_in[27];
    const float* d_w2 = (const float*)d_in[28];
    const float* d_b2 = (const float*)d_in[29];
    const float* ow = (const float*)d_in[30];
    const float* ob = (const float*)d_in[31];

    float *c1, *xe, *xd, *q, *k, *v, *z, *cm, *cs, *ao, *t1, *t2, *t3, *ff, *yv;
    __nv_bfloat16 *ah, *al, *bh, *bl;
    cudaGetSymbolAddress((void**)&c1, g_c1);
    cudaGetSymbolAddress((void**)&xe, g_xe);
    cudaGetSymbolAddress((void**)&xd, g_xd);
    cudaGetSymbolAddress((void**)&q,  g_q);
    cudaGetSymbolAddress((void**)&k,  g_k);
    cudaGetSymbolAddress((void**)&v,  g_v);
    cudaGetSymbolAddress((void**)&z,  g_z);
    cudaGetSymbolAddress((void**)&cm, g_cmax);
    cudaGetSymbolAddress((void**)&cs, g_csum);
    cudaGetSymbolAddress((void**)&ao, g_ao);
    cudaGetSymbolAddress((void**)&t1, g_t1);
    cudaGetSymbolAddress((void**)&t2, g_t2);
    cudaGetSymbolAddress((void**)&t3, g_t3);
    cudaGetSymbolAddress((void**)&ff, g_ff);
    cudaGetSymbolAddress((void**)&yv, g_y);
    cudaGetSymbolAddress((void**)&ah, g_ah);
    cudaGetSymbolAddress((void**)&al, g_al);
    cudaGetSymbolAddress((void**)&bh, g_bh);
    cudaGetSymbolAddress((void**)&bl, g_bl);

    cudaFuncSetAttribute(mma_gemm_k, cudaFuncAttributeMaxDynamicSharedMemorySize, 81920);

    const int M = 43200;
    const unsigned smem_bytes = 81920;
    dim3 agrid(900, 8);
    dim3 g256(2, 338);
    dim3 g1024(8, 338);
    const float* nobias = 0;

    split_w_k<<<320, 256>>>(c1w, bh, bl, 256, 288, 320);
    im2col1_k<<<54000, 256>>>(X_en, ah, al);
    mma_gemm_k<<<g256, 256, smem_bytes>>>(ah, al, bh, bl, c1b, c1, M, 256, 320, 2);
    split_w_k<<<2304, 256>>>(c2w, bh, bl, 256, 2304, 2304);
    im2col2_k<<<388800, 256>>>(c1, ah, al);
    mma_gemm_k<<<g256, 256, smem_bytes>>>(ah, al, bh, bl, c2b, xe, M, 256, 2304, 2);

    split_w_k<<<320, 256>>>(c1w, bh, bl, 256, 288, 320);
    im2col1_k<<<54000, 256>>>(X_de, ah, al);
    mma_gemm_k<<<g256, 256, smem_bytes>>>(ah, al, bh, bl, c1b, c1, M, 256, 320, 2);
    split_w_k<<<2304, 256>>>(c2w, bh, bl, 256, 2304, 2304);
    im2col2_k<<<388800, 256>>>(c1, ah, al);
    mma_gemm_k<<<g256, 256, smem_bytes>>>(ah, al, bh, bl, c2b, xd, M, 256, 2304, 2);

    split_act_k<<<43200, 256>>>(xe, ah, al, 11059200u);
    split_w_k<<<256, 256>>>(enc_wq, bh, bl, 256, 256, 256);
    mma_gemm_k<<<g256, 256, smem_bytes>>>(ah, al, bh, bl, nobias, q, M, 256, 256, 0);
    split_w_k<<<256, 256>>>(enc_wk, bh, bl, 256, 256, 256);
    mma_gemm_k<<<g256, 256, smem_bytes>>>(ah, al, bh, bl, nobias, k, M, 256, 256, 0);
    split_w_k<<<256, 256>>>(enc_wv, bh, bl, 256, 256, 256);
    mma_gemm_k<<<g256, 256, smem_bytes>>>(ah, al, bh, bl, nobias, v, M, 256, 256, 0);
    attn_scores_k<<<agrid, 256>>>(q, k, enc_rel, z);
    col_max_k<<<72, 256>>>(z, cm);
    col_expsum_k<<<72, 256>>>(z, cm, cs);
    attn_out_k<<<agrid, 256>>>(z, cs, v, ao);
    add_ln_k<<<43200, 256>>>(xe, ao, t1);
    split_act_k<<<43200, 256>>>(t1, ah, al, 11059200u);
    split_w_k<<<1024, 256>>>(e_w1, bh, bl, 1024, 256, 256);
    mma_gemm_k<<<g1024, 256, smem_bytes>>>(ah, al, bh, bl, e_b1, ff, M, 1024, 256, 1);
    split_act_k<<<172800, 256>>>(ff, ah, al, 44236800u);
    split_w_k<<<1024, 256>>>(e_w2, bh, bl, 256, 1024, 1024);
    mma_gemm_k<<<g256, 256, smem_bytes>>>(ah, al, bh, bl, e_b2, ao, M, 256, 1024, 0);
    add_ln_k<<<43200, 256>>>(t1, ao, t2);

    split_act_k<<<43200, 256>>>(xd, ah, al, 11059200u);
    split_w_k<<<256, 256>>>(m_wq, bh, bl, 256, 256, 256);
    mma_gemm_k<<<g256, 256, smem_bytes>>>(ah, al, bh, bl, nobias, q, M, 256, 256, 0);
    split_w_k<<<256, 256>>>(m_wk, bh, bl, 256, 256, 256);
    mma_gemm_k<<<g256, 256, smem_bytes>>>(ah, al, bh, bl, nobias, k, M, 256, 256, 0);
    split_w_k<<<256, 256>>>(m_wv, bh, bl, 256, 256, 256);
    mma_gemm_k<<<g256, 256, smem_bytes>>>(ah, al, bh, bl, nobias, v, M, 256, 256, 0);
    attn_scores_masked_k<<<agrid, 256>>>(q, k, m_rel, l1w, l1b, l2w, l2b, z);
    col_max_k<<<72, 256>>>(z, cm);
    col_expsum_k<<<72, 256>>>(z, cm, cs);
    attn_out_k<<<agrid, 256>>>(z, cs, v, ao);
    add_ln_k<<<43200, 256>>>(xd, ao, t1);

    split_act_k<<<43200, 256>>>(t1, ah, al, 11059200u);
    split_w_k<<<256, 256>>>(c_wq, bh, bl, 256, 256, 256);
    mma_gemm_k<<<g256, 256, smem_bytes>>>(ah, al, bh, bl, nobias, q, M, 256, 256, 0);
    split_act_k<<<43200, 256>>>(t2, ah, al, 11059200u);
    split_w_k<<<256, 256>>>(c_wk, bh, bl, 256, 256, 256);
    mma_gemm_k<<<g256, 256, smem_bytes>>>(ah, al, bh, bl, nobias, k, M, 256, 256, 0);
    split_w_k<<<256, 256>>>(c_wv, bh, bl, 256, 256, 256);
    mma_gemm_k<<<g256, 256, smem_bytes>>>(ah, al, bh, bl, nobias, v, M, 256, 256, 0);
    attn_scores_k<<<agrid, 256>>>(q, k, c_rel, z);
    col_max_k<<<72, 256>>>(z, cm);
    col_expsum_k<<<72, 256>>>(z, cm, cs);
    attn_out_k<<<agrid, 256>>>(z, cs, v, ao);
    add_ln_k<<<43200, 256>>>(ao, t1, t3);
    split_act_k<<<43200, 256>>>(t3, ah, al, 11059200u);
    split_w_k<<<1024, 256>>>(d_w1, bh, bl, 1024, 256, 256);
    mma_gemm_k<<<g1024, 256, smem_bytes>>>(ah, al, bh, bl, d_b1, ff, M, 1024, 256, 1);
    split_act_k<<<172800, 256>>>(ff, ah, al, 44236800u);
    split_w_k<<<1024, 256>>>(d_w2, bh, bl, 256, 1024, 1024);
    mma_gemm_k<<<g256, 256, smem_bytes>>>(ah, al, bh, bl, d_b2, ao, M, 256, 1024, 0);
    add_ln_k<<<43200, 256>>>(t3, ao, t1);

    outproj_k<<<5400, 256>>>(t1, ow, ob, yv);
    final_softmax_k<<<4, 256>>>(yv, (float*)d_out);
}

__device__ __forceinline__ unsigned smem_u32(const void* p)
{
    unsigned a;
    asm("{ .reg .u64 t; cvta.to.shared.u64 t, %1; cvt.u32.u64 %0, t; }" : "=r"(a) : "l"(p));
    return a;
}

__device__ __forceinline__ void mma16816(float* c, const unsigned* a, unsigned b0, unsigned b1)
{
    asm volatile("mma.sync.aligned.m16n8k16.row.col.f32.bf16.bf16.f32 {%0,%1,%2,%3}, {%4,%5,%6,%7}, {%8,%9}, {%0,%1,%2,%3};" : "+f"(c[0]), "+f"(c[1]), "+f"(c[2]), "+f"(c[3]) : "r"(a[0]), "r"(a[1]), "r"(a[2]), "r"(a[3]), "r"(b0), "r"(b1));
}

__device__ __forceinline__ void ldmx4(unsigned* r, unsigned addr)
{
    asm volatile("ldmatrix.sync.aligned.m8n8.x4.shared.b16 {%0,%1,%2,%3}, [%4];" : "=r"(r[0]), "=r"(r[1]), "=r"(r[2]), "=r"(r[3]) : "r"(addr));
}

__device__ __forceinline__ void stage_issue(
    const __nv_bfloat16* Ah, const __nv_bfloat16* Al,
    const __nv_bfloat16* Bh, const __nv_bfloat16* Bl,
    unsigned st, int m0, int n0, int M, int K, int koff, int tid)
{
    for (int j = 0; j < 8; j++) {
        int i = tid + j * 256;
        int t = i >> 9;
        int r = (i >> 2) & 127;
        int c = i & 3;
        const __nv_bfloat16* bp;
        int row;
        if (t < 2) {
            row = m0 + r;
            if (row >= M) row = M - 1;
            bp = (t == 1) ? Al : Ah;
        } else {
            row = n0 + r;
            bp = (t == 3) ? Bl : Bh;
        }
        const __nv_bfloat16* g = bp + (size_t)row * K + koff + c * 8;
        unsigned s = st + t * 10240 + r * 80 + c * 16;
        asm volatile("cp.async.ca.shared.global [%0], [%1], 16;" :: "r"(s), "l"(g) : "memory");
    }
    asm volatile("cp.async.commit_group;" ::: "memory");
}

__global__ __launch_bounds__(256, 1) void mma_gemm_k(
    const __nv_bfloat16* Ah, const __nv_bfloat16* Al,
    const __nv_bfloat16* Bh, const __nv_bfloat16* Bl,
    const float* bias, float* C, int M, int N, int K, int mode)
{
    extern __shared__ char smem[];
    const int tid = threadIdx.x;
    const int m0 = blockIdx.y * 128;
    const int n0 = blockIdx.x * 128;
    const int warp = tid >> 5;
    const int lane = tid & 31;
    const int wm = warp & 3;
    const int wn = warp >> 2;
    const int gid = lane >> 2;
    const int tig = lane & 3;
    const unsigned sbase = smem_u32(smem);

    const int arow = wm * 32 + (lane & 15);
    const int acolb = ((lane >> 4) & 1) * 16;
    const int nrow = (lane & 7) + ((lane >> 4) & 1) * 8;
    const int bcolb = ((lane >> 3) & 1) * 16;

    float acc[2][8][4];
    for (int mf = 0; mf < 2; mf++)
        for (int nf = 0; nf < 8; nf++)
            for (int e = 0; e < 4; e++)
                acc[mf][nf][e] = 0.f;

    const int nk = K >> 5;
    stage_issue(Ah, Al, Bh, Bl, sbase, m0, n0, M, K, 0, tid);

    for (int kb = 0; kb < nk; kb++) {
        if (kb + 1 < nk) {
            stage_issue(Ah, Al, Bh, Bl, sbase + ((kb + 1) & 1) * 40960, m0, n0, M, K, (kb + 1) * 32, tid);
            asm volatile("cp.async.wait_group 1;" ::: "memory");
        } else {
            asm volatile("cp.async.wait_group 0;" ::: "memory");
        }
        __syncthreads();

        const unsigned st = sbase + (kb & 1) * 40960;
        for (int ks = 0; ks < 2; ks++) {
            const int kbyte = ks * 32;
            unsigned afh[2][4];
            unsigned afl[2][4];
            for (int mf = 0; mf < 2; mf++) {
                const unsigned arowoff = (unsigned)(arow + mf * 16) * 80u + kbyte + acolb;
                ldmx4(afh[mf], st + arowoff);
                ldmx4(afl[mf], st + 10240u + arowoff);
            }
            for (int nfg = 0; nfg < 4; nfg++) {
                const unsigned browoff = (unsigned)(wn * 64 + nfg * 16 + nrow) * 80u + kbyte + bcolb;
                unsigned bh4[4];
                unsigned bl4[4];
                ldmx4(bh4, st + 20480u + browoff);
                ldmx4(bl4, st + 30720u + browoff);
                for (int sub = 0; sub < 2; sub++) {
                    const int nf = nfg * 2 + sub;
                    const unsigned b0h = bh4[sub * 2];
                    const unsigned b1h = bh4[sub * 2 + 1];
                    const unsigned b0l = bl4[sub * 2];
                    const unsigned b1l = bl4[sub * 2 + 1];
                    for (int mf = 0; mf < 2; mf++) {
                        mma16816(acc[mf][nf], afh[mf], b0h, b1h);
                        mma16816(acc[mf][nf], afh[mf], b0l, b1l);
                        mma16816(acc[mf][nf], afl[mf], b0h, b1h);
                    }
                }
            }
        }
        __syncthreads();
    }

    for (int mf = 0; mf < 2; mf++) {
        for (int nf = 0; nf < 8; nf++) {
            const int col = n0 + wn * 64 + nf * 8 + tig * 2;
            float bv0 = 0.f;
            float bv1 = 0.f;
            if (bias) {
                bv0 = bias[col];
                bv1 = bias[col + 1];
            }
            for (int half = 0; half < 2; half++) {
                const int m = m0 + wm * 32 + mf * 16 + gid + half * 8;
                if (m < M) {
                    float v0 = acc[mf][nf][half * 2 + 0] + bv0;
                    float v1 = acc[mf][nf][half * 2 + 1] + bv1;
                    if (mode == 1) {
                        v0 = fmaxf(v0, 0.f);
                        v1 = fmaxf(v1, 0.f);
                    }
                    if (mode == 2) {
                        const int b = m / 900;
                        const int p = m - b * 900;
                        float* ob = C + (size_t)b * 230400 + (size_t)col * 900 + p;
                        ob[0] = v0;
                        ob[900] = v1;
                    } else {
                        float2 stv;
                        stv.x = v0;
                        stv.y = v1;
                        *(float2*)(C + (size_t)m * N + col) = stv;
                    }
                }
            }
        }
    }
}

__global__ __launch_bounds__(256) void split_act_k(const float* x,
    __nv_bfloat16* hi, __nv_bfloat16* lo, unsigned n)
{
    unsigned i = blockIdx.x * 256u + threadIdx.x;
    if (i >= n) return;
    float v = x[i];
    __nv_bfloat16 h = __float2bfloat16(v);
    hi[i] = h;
    lo[i] = __float2bfloat16(v - __bfloat162float(h));
}

__global__ __launch_bounds__(256) void split_w_k(const float* w,
    __nv_bfloat16* hi, __nv_bfloat16* lo, int N, int K, int Kp)
{
    int i = blockIdx.x * 256 + threadIdx.x;
    if (i >= N * Kp) return;
    int r = i / Kp;
    int k = i - r * Kp;
    float v = 0.f;
    if (k < K) v = w[(size_t)r * K + k];
    __nv_bfloat16 h = __float2bfloat16(v);
    hi[i] = h;
    lo[i] = __float2bfloat16(v - __bfloat162float(h));
}

__global__ __launch_bounds__(256) void im2col1_k(const float* X,
    __nv_bfloat16* hi, __nv_bfloat16* lo)
{
    unsigned i = blockIdx.x * 256u + threadIdx.x;
    if (i >= 13824000u) return;
    int m = (int)(i / 320u);
    int k = (int)(i - (unsigned)m * 320u);
    float v = 0.f;
    if (k < 288) {
        int ic = k / 9;
        int r9 = k - ic * 9;
        int ky = r9 / 3;
        int kx = r9 - ky * 3;
        int b = m / 900;
        int p = m - b * 900;
        int y = p / 30;
        int x = p - y * 30;
        v = X[((size_t)(b * 32 + ic) * 32 + (y + ky)) * 32 + (x + kx)];
    }
    __nv_bfloat16 h = __float2bfloat16(v);
    hi[i] = h;
    lo[i] = __float2bfloat16(v - __bfloat162float(h));
}

__global__ __launch_bounds__(256) void im2col2_k(const float* in,
    __nv_bfloat16* hi, __nv_bfloat16* lo)
{
    unsigned i = blockIdx.x * 256u + threadIdx.x;
    if (i >= 99532800u) return;
    int m = (int)(i / 2304u);
    int k = (int)(i - (unsigned)m * 2304u);
    int ic = k / 9;
    int r9 = k - ic * 9;
    int ky = r9 / 3;
    int kx = r9 - ky * 3;
    int b = m / 900;
    int p = m - b * 900;
    int y = p / 30;
    int x = p - y * 30;
    int iy = y + ky - 1;
    int ix = x + kx - 1;
    float v = 0.f;
    if (iy >= 0 && iy < 30 && ix >= 0 && ix < 30) {
        v = in[(size_t)(b * 256 + ic) * 900 + iy * 30 + ix];
    }
    __nv_bfloat16 h = __float2bfloat16(v);
    hi[i] = h;
    lo[i] = __float2bfloat16(v - __bfloat162float(h));
}

__global__ __launch_bounds__(256) void attn_scores_k(
    const float* Q, const float* Kb, const float* RW, float* Z)
{
    const int s = blockIdx.x;
    const int h = blockIdx.y;
    const int tid = threadIdx.x;
    __shared__ float sq[48][33];
    __shared__ float sk[48][33];
    __shared__ float sw[32][49];
    __shared__ float se[48][49];
    for (int e = tid; e < 1536; e += 256) {
        int i = e >> 5;
        int d = e & 31;
        sq[i][d] = Q [((size_t)(s * 48 + i)) * 256 + h * 32 + d];
        sk[i][d] = Kb[((size_t)(s * 48 + i)) * 256 + h * 32 + d];
    }
    for (int e = tid; e < 1536; e += 256) {
        int d = e / 48;
        int j = e - d * 48;
        sw[d][j] = RW[(((size_t)s * 8 + h) * 32 + d) * 48 + j];
    }
    __syncthreads();
    float scv[9];
    for (int it = 0; it < 9; it++) {
        int e = tid + it * 256;
        int i = e / 48;
        int j = e - i * 48;
        float sc = 0.f;
        float em = 0.f;
        for (int d = 0; d < 32; d++) {
            float qv = sq[i][d];
            sc += qv * sk[j][d];
            em += qv * sw[d][j];
        }
        scv[it] = sc * 0.17677669529663689f;
        se[i][j] = em;
    }
    __syncthreads();
    size_t base = (size_t)s * 18432 + (size_t)h * 2304;
    for (int it = 0; it < 9; it++) {
        int e = tid + it * 256;
        int i = e / 48;
        int j = e - i * 48;
        float zz = scv[it];
        if (j <= i) zz += se[i][47 - i + j];
        Z[base + e] = zz;
    }
}

__global__ __launch_bounds__(256) void attn_scores_masked_k(
    const float* Q, const float* Kb, const float* RW,
    const float* L1w, const float* L1b,
    const float* L2w, const float* L2b, float* Z)
{
    const int s = blockIdx.x;
    const int h = blockIdx.y;
    const int tid = threadIdx.x;
    __shared__ float sq[48][33];
    __shared__ float sk[48][33];
    __shared__ float sw[32][49];
    __shared__ float se[48][49];
    __shared__ float ss[48][49];
    __shared__ float s1[48][49];
    for (int e = tid; e < 1536; e += 256) {
        int i = e >> 5;
        int d = e & 31;
        sq[i][d] = Q [((size_t)(s * 48 + i)) * 256 + h * 32 + d];
        sk[i][d] = Kb[((size_t)(s * 48 + i)) * 256 + h * 32 + d];
    }
    for (int e = tid; e < 1536; e += 256) {
        int d = e / 48;
        int j = e - d * 48;
        sw[d][j] = RW[(((size_t)s * 8 + h) * 32 + d) * 48 + j];
    }
    __syncthreads();
    for (int e = tid; e < 2304; e += 256) {
        int i = e / 48;
        int j = e - i * 48;
        float sc = 0.f;
        float em = 0.f;
        for (int d = 0; d < 32; d++) {
            float qv = sq[i][d];
            sc += qv * sk[j][d];
            em += qv * sw[d][j];
        }
        ss[i][j] = sc * 0.17677669529663689f;
        se[i][j] = em;
    }
    __syncthreads();
    for (int e = tid; e < 2304; e += 256) {
        int i = e / 48;
        int j = e - i * 48;
        float acc = L1b[j];
        for (int c = 0; c < 48; c++) acc += ss[i][c] * __ldg(&L1w[j * 48 + c]);
        s1[i][j] = acc;
    }
    __syncthreads();
    size_t base = (size_t)s * 18432 + (size_t)h * 2304;
    for (int e = tid; e < 2304; e += 256) {
        int a = e / 48;
        int b = e - a * 48;
        float acc = L2b[b];
        for (int c = 0; c < 48; c++) acc += s1[c][a] * __ldg(&L2w[b * 48 + c]);
        if (b > a) acc -= 3.402823466e+38f;
        if (b <= a) acc += se[a][47 - a + b];
        Z[base + e] = acc;
    }
}

__global__ __launch_bounds__(256) void col_max_k(const float* Z, float* cmax)
{
    int c = blockIdx.x * 256 + threadIdx.x;
    const float* p = Z + c;
    float m = -3.402823466e+38f;
    for (int s = 0; s < 900; s++) m = fmaxf(m, p[(size_t)s * 18432]);
    cmax[c] = m;
}

__global__ __launch_bounds__(256) void col_expsum_k(float* Z, const float* cmax, float* csum)
{
    int c = blockIdx.x * 256 + threadIdx.x;
    float m = cmax[c];
    float* p = Z + c;
    float sum = 0.f;
    for (int s = 0; s < 900; s++) {
        float v = __expf(p[(size_t)s * 18432] - m);
        p[(size_t)s * 18432] = v;
        sum += v;
    }
    csum[c] = sum;
}

__global__ __launch_bounds__(256) void attn_out_k(
    const float* Z, const float* csum, const float* V, float* O)
{
    const int s = blockIdx.x;
    const int h = blockIdx.y;
    const int tid = threadIdx.x;
    __shared__ float sp[48][49];
    __shared__ float sv[48][33];
    size_t base = (size_t)s * 18432 + (size_t)h * 2304;
    for (int e = tid; e < 2304; e += 256) {
        int i = e / 48;
        int j = e - i * 48;
        sp[i][j] = Z[base + e] / csum[h * 2304 + e];
    }
    for (int e = tid; e < 1536; e += 256) {
        int j = e >> 5;
        int d = e & 31;
        sv[j][d] = V[((size_t)(s * 48 + j)) * 256 + h * 32 + d];
    }
    __syncthreads();
    for (int e = tid; e < 1536; e += 256) {
        int i = e >> 5;
        int d = e & 31;
        float acc = 0.f;
        for (int j = 0; j < 48; j++) acc += sp[i][j] * sv[j][d];
        O[(size_t)((s * 8 + h) * 48 + i) * 32 + d] = acc;
    }
}

__device__ __forceinline__ float block_sum256(float v, float* sbuf)
{
    for (int o = 16; o > 0; o >>= 1) v += __shfl_down_sync(0xffffffffu, v, o);
    int w = threadIdx.x >> 5;
    int l = threadIdx.x & 31;
    if (l == 0) sbuf[w] = v;
    __syncthreads();
    if (w == 0) {
        v = (l < 8) ? sbuf[l] : 0.f;
        for (int o = 4; o > 0; o >>= 1) v += __shfl_down_sync(0xffffffffu, v, o);
        if (l == 0) sbuf[0] = v;
    }
    __syncthreads();
    float r = sbuf[0];
    __syncthreads();
    return r;
}

__global__ __launch_bounds__(256) void add_ln_k(const float* A, const float* B, float* O)
{
    __shared__ float sbuf[8];
    size_t base = (size_t)blockIdx.x * 256;
    float v = A[base + threadIdx.x] + B[base + threadIdx.x];
    float mean = block_sum256(v, sbuf) * (1.f / 256.f);
    float d = v - mean;
    float var = block_sum256(d * d, sbuf) * (1.f / 256.f);
    O[base + threadIdx.x] = d * rsqrtf(var + 1e-5f);
}

__global__ __launch_bounds__(256) void outproj_k(const float* H, const float* w,
                                                 const float* b, float* y)
{
    int warp = (blockIdx.x * 256 + threadIdx.x) >> 5;
    int lane = threadIdx.x & 31;
    if (warp >= 43200) return;
    const float* row = H + (size_t)warp * 256;
    float s = 0.f;
    for (int k = lane; k < 256; k += 32) s += row[k] * w[k];
    for (int o = 16; o > 0; o >>= 1) s += __shfl_down_sync(0xffffffffu, s, o);
    if (lane == 0) y[warp] = s + b[0];
}

__global__ __launch_bounds__(256) void final_softmax_k(const float* y, float* out)
{
    int s = blockIdx.x * 256 + threadIdx.x;
    if (s >= 900) return;
    float m = -3.402823466e+38f;
    for (int b = 0; b < 48; b++) m = fmaxf(m, y[b * 900 + s]);
    float sum = 0.f;
    for (int b = 0; b < 48; b++) sum += __expf(y[b * 900 + s] - m);
    float inv = 1.f / sum;
    for (int b = 0; b < 48; b++) out[b * 900 + s] = __expf(y[b * 900 + s] - m) * inv;
}

// round 11
// speedup vs baseline: 1.0546x; 1.0546x over previous
#include <cuda_runtime.h>
#include <cuda_bf16.h>
#include <cstdint>
#include <math.h>

__device__ float g_c1[48*256*900];
__device__ float g_xe[48*256*900];
__device__ float g_xd[48*256*900];
__device__ float g_q [48*900*256];
__device__ float g_k [48*900*256];
__device__ float g_v [48*900*256];
__device__ float g_z [900*8*48*48];
__device__ float g_cmax[8*48*48];
__device__ float g_csum[8*48*48];
__device__ float g_ao[48*900*256];
__device__ float g_t1[48*900*256];
__device__ float g_t2[48*900*256];
__device__ float g_t3[48*900*256];
__device__ float g_ff[48*900*1024];
__device__ float g_y [48*900];
__device__ __nv_bfloat16 g_ah[99532800u];
__device__ __nv_bfloat16 g_al[99532800u];
__device__ __nv_bfloat16 g_bh[2359296u];
__device__ __nv_bfloat16 g_bl[2359296u];

__global__ void mma_gemm_k(const __nv_bfloat16* Ah, const __nv_bfloat16* Al,
                           const __nv_bfloat16* Bh, const __nv_bfloat16* Bl,
                           const float* bias, float* C, int M, int N, int K, int mode);
__global__ void split_act_k(const float* x, __nv_bfloat16* hi, __nv_bfloat16* lo, unsigned n);
__global__ void split_w_k(const float* w, __nv_bfloat16* hi, __nv_bfloat16* lo, int N, int K, int Kp);
__global__ void im2col1_k(const float* X, __nv_bfloat16* hi, __nv_bfloat16* lo);
__global__ void im2col2_k(const float* in, __nv_bfloat16* hi, __nv_bfloat16* lo);
__global__ void attn_scores_k(const float* Q, const float* Kb, const float* RW, float* Z);
__global__ void attn_scores_masked_k(const float* Q, const float* Kb, const float* RW,
                                     const float* L1w, const float* L1b,
                                     const float* L2w, const float* L2b, float* Z);
__global__ void col_max_k(const float* Z, float* cmax);
__global__ void col_expsum_k(float* Z, const float* cmax, float* csum);
__global__ void attn_out_k(const float* Z, const float* csum, const float* V, float* O);
__global__ void add_ln_k(const float* A, const float* B, float* O);
__global__ void outproj_k(const float* H, const float* w, const float* b, float* y);
__global__ void final_softmax_k(const float* y, float* out);

extern "C" void kernel_launch(void* const* d_in, const int* in_sizes, int n_in,
                              void* d_out, int out_size)
{
    const float* X_en = (const float*)d_in[0];
    const float* X_de = (const float*)d_in[1];
    const float* c1w = (const float*)d_in[2];
    const float* c1b = (const float*)d_in[3];
    const float* c2w = (const float*)d_in[4];
    const float* c2b = (const float*)d_in[5];
    const float* enc_wq = (const float*)d_in[6];
    const float* enc_wk = (const float*)d_in[7];
    const float* enc_wv = (const float*)d_in[8];
    const float* enc_rel = (const float*)d_in[9];
    const float* e_w1 = (const float*)d_in[10];
    const float* e_b1 = (const float*)d_in[11];
    const float* e_w2 = (const float*)d_in[12];
    const float* e_b2 = (const float*)d_in[13];
    const float* m_wq = (const float*)d_in[14];
    const float* m_wk = (const float*)d_in[15];
    const float* m_wv = (const float*)d_in[16];
    const float* m_rel = (const float*)d_in[17];
    const float* l1w = (const float*)d_in[18];
    const float* l1b = (const float*)d_in[19];
    const float* l2w = (const float*)d_in[20];
    const float* l2b = (const float*)d_in[21];
    const float* c_wq = (const float*)d_in[22];
    const float* c_wk = (const float*)d_in[23];
    const float* c_wv = (const float*)d_in[24];
    const float* c_rel = (const float*)d_in[25];
    const float* d_w1 = (const float*)d_in[26];
    const float* d_b1 = (const float*)d_in[27];
    const float* d_w2 = (const float*)d_in[28];
    const float* d_b2 = (const float*)d_in[29];
    const float* ow = (const float*)d_in[30];
    const float* ob = (const float*)d_in[31];

    float *c1, *xe, *xd, *q, *k, *v, *z, *cm, *cs, *ao, *t1, *t2, *t3, *ff, *yv;
    __nv_bfloat16 *ah, *al, *bh, *bl;
    cudaGetSymbolAddress((void**)&c1, g_c1);
    cudaGetSymbolAddress((void**)&xe, g_xe);
    cudaGetSymbolAddress((void**)&xd, g_xd);
    cudaGetSymbolAddress((void**)&q,  g_q);
    cudaGetSymbolAddress((void**)&k,  g_k);
    cudaGetSymbolAddress((void**)&v,  g_v);
    cudaGetSymbolAddress((void**)&z,  g_z);
    cudaGetSymbolAddress((void**)&cm, g_cmax);
    cudaGetSymbolAddress((void**)&cs, g_csum);
    cudaGetSymbolAddress((void**)&ao, g_ao);
    cudaGetSymbolAddress((void**)&t1, g_t1);
    cudaGetSymbolAddress((void**)&t2, g_t2);
    cudaGetSymbolAddress((void**)&t3, g_t3);
    cudaGetSymbolAddress((void**)&ff, g_ff);
    cudaGetSymbolAddress((void**)&yv, g_y);
    cudaGetSymbolAddress((void**)&ah, g_ah);
    cudaGetSymbolAddress((void**)&al, g_al);
    cudaGetSymbolAddress((void**)&bh, g_bh);
    cudaGetSymbolAddress((void**)&bl, g_bl);

    cudaFuncSetAttribute(mma_gemm_k, cudaFuncAttributeMaxDynamicSharedMemorySize, 81920);

    const int M = 43200;
    const unsigned smem_bytes = 81920;
    dim3 agrid(900, 8);
    dim3 g256(2, 338);
    dim3 g1024(8, 338);
    const float* nobias = 0;

    split_w_k<<<320, 256>>>(c1w, bh, bl, 256, 288, 320);
    im2col1_k<<<54000, 256>>>(X_en, ah, al);
    mma_gemm_k<<<g256, 256, smem_bytes>>>(ah, al, bh, bl, c1b, c1, M, 256, 320, 2);
    split_w_k<<<2304, 256>>>(c2w, bh, bl, 256, 2304, 2304);
    im2col2_k<<<388800, 256>>>(c1, ah, al);
    mma_gemm_k<<<g256, 256, smem_bytes>>>(ah, al, bh, bl, c2b, xe, M, 256, 2304, 2);

    split_w_k<<<320, 256>>>(c1w, bh, bl, 256, 288, 320);
    im2col1_k<<<54000, 256>>>(X_de, ah, al);
    mma_gemm_k<<<g256, 256, smem_bytes>>>(ah, al, bh, bl, c1b, c1, M, 256, 320, 2);
    split_w_k<<<2304, 256>>>(c2w, bh, bl, 256, 2304, 2304);
    im2col2_k<<<388800, 256>>>(c1, ah, al);
    mma_gemm_k<<<g256, 256, smem_bytes>>>(ah, al, bh, bl, c2b, xd, M, 256, 2304, 2);

    split_act_k<<<43200, 256>>>(xe, ah, al, 11059200u);
    split_w_k<<<256, 256>>>(enc_wq, bh, bl, 256, 256, 256);
    mma_gemm_k<<<g256, 256, smem_bytes>>>(ah, al, bh, bl, nobias, q, M, 256, 256, 0);
    split_w_k<<<256, 256>>>(enc_wk, bh, bl, 256, 256, 256);
    mma_gemm_k<<<g256, 256, smem_bytes>>>(ah, al, bh, bl, nobias, k, M, 256, 256, 0);
    split_w_k<<<256, 256>>>(enc_wv, bh, bl, 256, 256, 256);
    mma_gemm_k<<<g256, 256, smem_bytes>>>(ah, al, bh, bl, nobias, v, M, 256, 256, 0);
    attn_scores_k<<<agrid, 256>>>(q, k, enc_rel, z);
    col_max_k<<<72, 256>>>(z, cm);
    col_expsum_k<<<72, 256>>>(z, cm, cs);
    attn_out_k<<<agrid, 256>>>(z, cs, v, ao);
    add_ln_k<<<43200, 256>>>(xe, ao, t1);
    split_act_k<<<43200, 256>>>(t1, ah, al, 11059200u);
    split_w_k<<<1024, 256>>>(e_w1, bh, bl, 1024, 256, 256);
    mma_gemm_k<<<g1024, 256, smem_bytes>>>(ah, al, bh, bl, e_b1, ff, M, 1024, 256, 1);
    split_act_k<<<172800, 256>>>(ff, ah, al, 44236800u);
    split_w_k<<<1024, 256>>>(e_w2, bh, bl, 256, 1024, 1024);
    mma_gemm_k<<<g256, 256, smem_bytes>>>(ah, al, bh, bl, e_b2, ao, M, 256, 1024, 0);
    add_ln_k<<<43200, 256>>>(t1, ao, t2);

    split_act_k<<<43200, 256>>>(xd, ah, al, 11059200u);
    split_w_k<<<256, 256>>>(m_wq, bh, bl, 256, 256, 256);
    mma_gemm_k<<<g256, 256, smem_bytes>>>(ah, al, bh, bl, nobias, q, M, 256, 256, 0);
    split_w_k<<<256, 256>>>(m_wk, bh, bl, 256, 256, 256);
    mma_gemm_k<<<g256, 256, smem_bytes>>>(ah, al, bh, bl, nobias, k, M, 256, 256, 0);
    split_w_k<<<256, 256>>>(m_wv, bh, bl, 256, 256, 256);
    mma_gemm_k<<<g256, 256, smem_bytes>>>(ah, al, bh, bl, nobias, v, M, 256, 256, 0);
    attn_scores_masked_k<<<agrid, 256>>>(q, k, m_rel, l1w, l1b, l2w, l2b, z);
    col_max_k<<<72, 256>>>(z, cm);
    col_expsum_k<<<72, 256>>>(z, cm, cs);
    attn_out_k<<<agrid, 256>>>(z, cs, v, ao);
    add_ln_k<<<43200, 256>>>(xd, ao, t1);

    split_act_k<<<43200, 256>>>(t1, ah, al, 11059200u);
    split_w_k<<<256, 256>>>(c_wq, bh, bl, 256, 256, 256);
    mma_gemm_k<<<g256, 256, smem_bytes>>>(ah, al, bh, bl, nobias, q, M, 256, 256, 0);
    split_act_k<<<43200, 256>>>(t2, ah, al, 11059200u);
    split_w_k<<<256, 256>>>(c_wk, bh, bl, 256, 256, 256);
    mma_gemm_k<<<g256, 256, smem_bytes>>>(ah, al, bh, bl, nobias, k, M, 256, 256, 0);
    split_w_k<<<256, 256>>>(c_wv, bh, bl, 256, 256, 256);
    mma_gemm_k<<<g256, 256, smem_bytes>>>(ah, al, bh, bl, nobias, v, M, 256, 256, 0);
    attn_scores_k<<<agrid, 256>>>(q, k, c_rel, z);
    col_max_k<<<72, 256>>>(z, cm);
    col_expsum_k<<<72, 256>>>(z, cm, cs);
    attn_out_k<<<agrid, 256>>>(z, cs, v, ao);
    add_ln_k<<<43200, 256>>>(ao, t1, t3);
    split_act_k<<<43200, 256>>>(t3, ah, al, 11059200u);
    split_w_k<<<1024, 256>>>(d_w1, bh, bl, 1024, 256, 256);
    mma_gemm_k<<<g1024, 256, smem_bytes>>>(ah, al, bh, bl, d_b1, ff, M, 1024, 256, 1);
    split_act_k<<<172800, 256>>>(ff, ah, al, 44236800u);
    split_w_k<<<1024, 256>>>(d_w2, bh, bl, 256, 1024, 1024);
    mma_gemm_k<<<g256, 256, smem_bytes>>>(ah, al, bh, bl, d_b2, ao, M, 256, 1024, 0);
    add_ln_k<<<43200, 256>>>(t3, ao, t1);

    outproj_k<<<5400, 256>>>(t1, ow, ob, yv);
    final_softmax_k<<<4, 256>>>(yv, (float*)d_out);
}

__device__ __forceinline__ unsigned smem_u32(const void* p)
{
    unsigned a;
    asm("{ .reg .u64 t; cvta.to.shared.u64 t, %1; cvt.u32.u64 %0, t; }" : "=r"(a) : "l"(p));
    return a;
}

__device__ __forceinline__ void mma16816(float* c, const unsigned* a, unsigned b0, unsigned b1)
{
    asm volatile("mma.sync.aligned.m16n8k16.row.col.f32.bf16.bf16.f32 {%0,%1,%2,%3}, {%4,%5,%6,%7}, {%8,%9}, {%0,%1,%2,%3};" : "+f"(c[0]), "+f"(c[1]), "+f"(c[2]), "+f"(c[3]) : "r"(a[0]), "r"(a[1]), "r"(a[2]), "r"(a[3]), "r"(b0), "r"(b1));
}

__device__ __forceinline__ void ldmx4(unsigned* r, unsigned addr)
{
    asm volatile("ldmatrix.sync.aligned.m8n8.x4.shared.b16 {%0,%1,%2,%3}, [%4];" : "=r"(r[0]), "=r"(r[1]), "=r"(r[2]), "=r"(r[3]) : "r"(addr));
}

__device__ __forceinline__ void stage_issue(
    const __nv_bfloat16* Ah, const __nv_bfloat16* Al,
    const __nv_bfloat16* Bh, const __nv_bfloat16* Bl,
    unsigned st, int m0, int n0, int M, int K, int koff, int tid)
{
    for (int j = 0; j < 8; j++) {
        int i = tid + j * 256;
        int t = i >> 9;
        int r = (i >> 2) & 127;
        int c = i & 3;
        const __nv_bfloat16* bp;
        int row;
        if (t < 2) {
            row = m0 + r;
            if (row >= M) row = M - 1;
            bp = (t == 1) ? Al : Ah;
        } else {
            row = n0 + r;
            bp = (t == 3) ? Bl : Bh;
        }
        const __nv_bfloat16* g = bp + (size_t)row * K + koff + c * 8;
        unsigned s = st + t * 10240 + r * 80 + c * 16;
        asm volatile("cp.async.ca.shared.global [%0], [%1], 16;" :: "r"(s), "l"(g) : "memory");
    }
    asm volatile("cp.async.commit_group;" ::: "memory");
}

__global__ __launch_bounds__(256, 2) void mma_gemm_k(
    const __nv_bfloat16* Ah, const __nv_bfloat16* Al,
    const __nv_bfloat16* Bh, const __nv_bfloat16* Bl,
    const float* bias, float* C, int M, int N, int K, int mode)
{
    extern __shared__ char smem[];
    const int tid = threadIdx.x;
    const int m0 = blockIdx.y * 128;
    const int n0 = blockIdx.x * 128;
    const int warp = tid >> 5;
    const int lane = tid & 31;
    const int wm = warp & 3;
    const int wn = warp >> 2;
    const int gid = lane >> 2;
    const int tig = lane & 3;
    const unsigned sbase = smem_u32(smem);

    const int arow = wm * 32 + (lane & 15);
    const int acolb = ((lane >> 4) & 1) * 16;
    const int nrow = (lane & 7) + ((lane >> 4) & 1) * 8;
    const int bcolb = ((lane >> 3) & 1) * 16;

    float acc[2][8][4];
    for (int mf = 0; mf < 2; mf++)
        for (int nf = 0; nf < 8; nf++)
            for (int e = 0; e < 4; e++)
                acc[mf][nf][e] = 0.f;

    const int nk = K >> 5;
    stage_issue(Ah, Al, Bh, Bl, sbase, m0, n0, M, K, 0, tid);

    for (int kb = 0; kb < nk; kb++) {
        if (kb + 1 < nk) {
            stage_issue(Ah, Al, Bh, Bl, sbase + ((kb + 1) & 1) * 40960, m0, n0, M, K, (kb + 1) * 32, tid);
            asm volatile("cp.async.wait_group 1;" ::: "memory");
        } else {
            asm volatile("cp.async.wait_group 0;" ::: "memory");
        }
        __syncthreads();

        const unsigned st = sbase + (kb & 1) * 40960;
        for (int ks = 0; ks < 2; ks++) {
            const int kbyte = ks * 32;
            unsigned afh[2][4];
            unsigned afl[2][4];
            for (int mf = 0; mf < 2; mf++) {
                const unsigned arowoff = (unsigned)(arow + mf * 16) * 80u + kbyte + acolb;
                ldmx4(afh[mf], st + arowoff);
                ldmx4(afl[mf], st + 10240u + arowoff);
            }
            for (int nfg = 0; nfg < 4; nfg++) {
                const unsigned browoff = (unsigned)(wn * 64 + nfg * 16 + nrow) * 80u + kbyte + bcolb;
                unsigned bh4[4];
                unsigned bl4[4];
                ldmx4(bh4, st + 20480u + browoff);
                ldmx4(bl4, st + 30720u + browoff);
                for (int sub = 0; sub < 2; sub++) {
                    const int nf = nfg * 2 + sub;
                    const unsigned b0h = bh4[sub * 2];
                    const unsigned b1h = bh4[sub * 2 + 1];
                    const unsigned b0l = bl4[sub * 2];
                    const unsigned b1l = bl4[sub * 2 + 1];
                    for (int mf = 0; mf < 2; mf++) {
                        mma16816(acc[mf][nf], afh[mf], b0h, b1h);
                        mma16816(acc[mf][nf], afh[mf], b0l, b1l);
                        mma16816(acc[mf][nf], afl[mf], b0h, b1h);
                    }
                }
            }
        }
        __syncthreads();
    }

    for (int mf = 0; mf < 2; mf++) {
        for (int nf = 0; nf < 8; nf++) {
            const int col = n0 + wn * 64 + nf * 8 + tig * 2;
            float bv0 = 0.f;
            float bv1 = 0.f;
            if (bias) {
                bv0 = bias[col];
                bv1 = bias[col + 1];
            }
            for (int half = 0; half < 2; half++) {
                const int m = m0 + wm * 32 + mf * 16 + gid + half * 8;
                if (m < M) {
                    float v0 = acc[mf][nf][half * 2 + 0] + bv0;
                    float v1 = acc[mf][nf][half * 2 + 1] + bv1;
                    if (mode == 1) {
                        v0 = fmaxf(v0, 0.f);
                        v1 = fmaxf(v1, 0.f);
                    }
                    if (mode == 2) {
                        const int b = m / 900;
                        const int p = m - b * 900;
                        float* ob = C + (size_t)b * 230400 + (size_t)col * 900 + p;
                        ob[0] = v0;
                        ob[900] = v1;
                    } else {
                        float2 stv;
                        stv.x = v0;
                        stv.y = v1;
                        *(float2*)(C + (size_t)m * N + col) = stv;
                    }
                }
            }
        }
    }
}

__global__ __launch_bounds__(256) void split_act_k(const float* x,
    __nv_bfloat16* hi, __nv_bfloat16* lo, unsigned n)
{
    unsigned i = blockIdx.x * 256u + threadIdx.x;
    if (i >= n) return;
    float v = x[i];
    __nv_bfloat16 h = __float2bfloat16(v);
    hi[i] = h;
    lo[i] = __float2bfloat16(v - __bfloat162float(h));
}

__global__ __launch_bounds__(256) void split_w_k(const float* w,
    __nv_bfloat16* hi, __nv_bfloat16* lo, int N, int K, int Kp)
{
    int i = blockIdx.x * 256 + threadIdx.x;
    if (i >= N * Kp) return;
    int r = i / Kp;
    int k = i - r * Kp;
    float v = 0.f;
    if (k < K) v = w[(size_t)r * K + k];
    __nv_bfloat16 h = __float2bfloat16(v);
    hi[i] = h;
    lo[i] = __float2bfloat16(v - __bfloat162float(h));
}

__global__ __launch_bounds__(256) void im2col1_k(const float* X,
    __nv_bfloat16* hi, __nv_bfloat16* lo)
{
    unsigned i = blockIdx.x * 256u + threadIdx.x;
    if (i >= 13824000u) return;
    int m = (int)(i / 320u);
    int k = (int)(i - (unsigned)m * 320u);
    float v = 0.f;
    if (k < 288) {
        int ic = k / 9;
        int r9 = k - ic * 9;
        int ky = r9 / 3;
        int kx = r9 - ky * 3;
        int b = m / 900;
        int p = m - b * 900;
        int y = p / 30;
        int x = p - y * 30;
        v = X[((size_t)(b * 32 + ic) * 32 + (y + ky)) * 32 + (x + kx)];
    }
    __nv_bfloat16 h = __float2bfloat16(v);
    hi[i] = h;
    lo[i] = __float2bfloat16(v - __bfloat162float(h));
}

__global__ __launch_bounds__(256) void im2col2_k(const float* in,
    __nv_bfloat16* hi, __nv_bfloat16* lo)
{
    unsigned i = blockIdx.x * 256u + threadIdx.x;
    if (i >= 99532800u) return;
    int m = (int)(i / 2304u);
    int k = (int)(i - (unsigned)m * 2304u);
    int ic = k / 9;
    int r9 = k - ic * 9;
    int ky = r9 / 3;
    int kx = r9 - ky * 3;
    int b = m / 900;
    int p = m - b * 900;
    int y = p / 30;
    int x = p - y * 30;
    int iy = y + ky - 1;
    int ix = x + kx - 1;
    float v = 0.f;
    if (iy >= 0 && iy < 30 && ix >= 0 && ix < 30) {
        v = in[(size_t)(b * 256 + ic) * 900 + iy * 30 + ix];
    }
    __nv_bfloat16 h = __float2bfloat16(v);
    hi[i] = h;
    lo[i] = __float2bfloat16(v - __bfloat162float(h));
}

__global__ __launch_bounds__(256) void attn_scores_k(
    const float* Q, const float* Kb, const float* RW, float* Z)
{
    const int s = blockIdx.x;
    const int h = blockIdx.y;
    const int tid = threadIdx.x;
    __shared__ float sq[48][33];
    __shared__ float sk[48][33];
    __shared__ float sw[32][49];
    __shared__ float se[48][49];
    for (int e = tid; e < 1536; e += 256) {
        int i = e >> 5;
        int d = e & 31;
        sq[i][d] = Q [((size_t)(s * 48 + i)) * 256 + h * 32 + d];
        sk[i][d] = Kb[((size_t)(s * 48 + i)) * 256 + h * 32 + d];
    }
    for (int e = tid; e < 1536; e += 256) {
        int d = e / 48;
        int j = e - d * 48;
        sw[d][j] = RW[(((size_t)s * 8 + h) * 32 + d) * 48 + j];
    }
    __syncthreads();
    float scv[9];
    for (int it = 0; it < 9; it++) {
        int e = tid + it * 256;
        int i = e / 48;
        int j = e - i * 48;
        float sc = 0.f;
        float em = 0.f;
        for (int d = 0; d < 32; d++) {
            float qv = sq[i][d];
            sc += qv * sk[j][d];
            em += qv * sw[d][j];
        }
        scv[it] = sc * 0.17677669529663689f;
        se[i][j] = em;
    }
    __syncthreads();
    size_t base = (size_t)s * 18432 + (size_t)h * 2304;
    for (int it = 0; it < 9; it++) {
        int e = tid + it * 256;
        int i = e / 48;
        int j = e - i * 48;
        float zz = scv[it];
        if (j <= i) zz += se[i][47 - i + j];
        Z[base + e] = zz;
    }
}

__global__ __launch_bounds__(256) void attn_scores_masked_k(
    const float* Q, const float* Kb, const float* RW,
    const float* L1w, const float* L1b,
    const float* L2w, const float* L2b, float* Z)
{
    const int s = blockIdx.x;
    const int h = blockIdx.y;
    const int tid = threadIdx.x;
    __shared__ float sq[48][33];
    __shared__ float sk[48][33];
    __shared__ float sw[32][49];
    __shared__ float se[48][49];
    __shared__ float ss[48][49];
    __shared__ float s1[48][49];
    for (int e = tid; e < 1536; e += 256) {
        int i = e >> 5;
        int d = e & 31;
        sq[i][d] = Q [((size_t)(s * 48 + i)) * 256 + h * 32 + d];
        sk[i][d] = Kb[((size_t)(s * 48 + i)) * 256 + h * 32 + d];
    }
    for (int e = tid; e < 1536; e += 256) {
        int d = e / 48;
        int j = e - d * 48;
        sw[d][j] = RW[(((size_t)s * 8 + h) * 32 + d) * 48 + j];
    }
    __syncthreads();
    for (int e = tid; e < 2304; e += 256) {
        int i = e / 48;
        int j = e - i * 48;
        float sc = 0.f;
        float em = 0.f;
        for (int d = 0; d < 32; d++) {
            float qv = sq[i][d];
            sc += qv * sk[j][d];
            em += qv * sw[d][j];
        }
        ss[i][j] = sc * 0.17677669529663689f;
        se[i][j] = em;
    }
    __syncthreads();
    for (int e = tid; e < 2304; e += 256) {
        int i = e / 48;
        int j = e - i * 48;
        float acc = L1b[j];
        for (int c = 0; c < 48; c++) acc += ss[i][c] * __ldg(&L1w[j * 48 + c]);
        s1[i][j] = acc;
    }
    __syncthreads();
    size_t base = (size_t)s * 18432 + (size_t)h * 2304;
    for (int e = tid; e < 2304; e += 256) {
        int a = e / 48;
        int b = e - a * 48;
        float acc = L2b[b];
        for (int c = 0; c < 48; c++) acc += s1[c][a] * __ldg(&L2w[b * 48 + c]);
        if (b > a) acc -= 3.402823466e+38f;
        if (b <= a) acc += se[a][47 - a + b];
        Z[base + e] = acc;
    }
}

__global__ __launch_bounds__(256) void col_max_k(const float* Z, float* cmax)
{
    int c = blockIdx.x * 256 + threadIdx.x;
    const float* p = Z + c;
    float m = -3.402823466e+38f;
    for (int s = 0; s < 900; s++) m = fmaxf(m, p[(size_t)s * 18432]);
    cmax[c] = m;
}

__global__ __launch_bounds__(256) void col_expsum_k(float* Z, const float* cmax, float* csum)
{
    int c = blockIdx.x * 256 + threadIdx.x;
    float m = cmax[c];
    float* p = Z + c;
    float sum = 0.f;
    for (int s = 0; s < 900; s++) {
        float v = __expf(p[(size_t)s * 18432] - m);
        p[(size_t)s * 18432] = v;
        sum += v;
    }
    csum[c] = sum;
}

__global__ __launch_bounds__(256) void attn_out_k(
    const float* Z, const float* csum, const float* V, float* O)
{
    const int s = blockIdx.x;
    const int h = blockIdx.y;
    const int tid = threadIdx.x;
    __shared__ float sp[48][49];
    __shared__ float sv[48][33];
    size_t base = (size_t)s * 18432 + (size_t)h * 2304;
    for (int e = tid; e < 2304; e += 256) {
        int i = e / 48;
        int j = e - i * 48;
        sp[i][j] = Z[base + e] / csum[h * 2304 + e];
    }
    for (int e = tid; e < 1536; e += 256) {
        int j = e >> 5;
        int d = e & 31;
        sv[j][d] = V[((size_t)(s * 48 + j)) * 256 + h * 32 + d];
    }
    __syncthreads();
    for (int e = tid; e < 1536; e += 256) {
        int i = e >> 5;
        int d = e & 31;
        float acc = 0.f;
        for (int j = 0; j < 48; j++) acc += sp[i][j] * sv[j][d];
        O[(size_t)((s * 8 + h) * 48 + i) * 32 + d] = acc;
    }
}

__device__ __forceinline__ float block_sum256(float v, float* sbuf)
{
    for (int o = 16; o > 0; o >>= 1) v += __shfl_down_sync(0xffffffffu, v, o);
    int w = threadIdx.x >> 5;
    int l = threadIdx.x & 31;
    if (l == 0) sbuf[w] = v;
    __syncthreads();
    if (w == 0) {
        v = (l < 8) ? sbuf[l] : 0.f;
        for (int o = 4; o > 0; o >>= 1) v += __shfl_down_sync(0xffffffffu, v, o);
        if (l == 0) sbuf[0] = v;
    }
    __syncthreads();
    float r = sbuf[0];
    __syncthreads();
    return r;
}

__global__ __launch_bounds__(256) void add_ln_k(const float* A, const float* B, float* O)
{
    __shared__ float sbuf[8];
    size_t base = (size_t)blockIdx.x * 256;
    float v = A[base + threadIdx.x] + B[base + threadIdx.x];
    float mean = block_sum256(v, sbuf) * (1.f / 256.f);
    float d = v - mean;
    float var = block_sum256(d * d, sbuf) * (1.f / 256.f);
    O[base + threadIdx.x] = d * rsqrtf(var + 1e-5f);
}

__global__ __launch_bounds__(256) void outproj_k(const float* H, const float* w,
                                                 const float* b, float* y)
{
    int warp = (blockIdx.x * 256 + threadIdx.x) >> 5;
    int lane = threadIdx.x & 31;
    if (warp >= 43200) return;
    const float* row = H + (size_t)warp * 256;
    float s = 0.f;
    for (int k = lane; k < 256; k += 32) s += row[k] * w[k];
    for (int o = 16; o > 0; o >>= 1) s += __shfl_down_sync(0xffffffffu, s, o);
    if (lane == 0) y[warp] = s + b[0];
}

__global__ __launch_bounds__(256) void final_softmax_k(const float* y, float* out)
{
    int s = blockIdx.x * 256 + threadIdx.x;
    if (s >= 900) return;
    float m = -3.402823466e+38f;
    for (int b = 0; b < 48; b++) m = fmaxf(m, y[b * 900 + s]);
    float sum = 0.f;
    for (int b = 0; b < 48; b++) sum += __expf(y[b * 900 + s] - m);
    float inv = 1.f / sum;
    for (int b = 0; b < 48; b++) out[b * 900 + s] = __expf(y[b * 900 + s] - m) * inv;
}

// round 12
// speedup vs baseline: 1.2598x; 1.1945x over previous
#include <cuda_runtime.h>
#include <cuda_fp16.h>
#include <cstdint>
#include <math.h>

__device__ float g_c1[48*256*900];
__device__ float g_xe[48*256*900];
__device__ float g_xd[48*256*900];
__device__ float g_q [48*900*256];
__device__ float g_k [48*900*256];
__device__ float g_v [48*900*256];
__device__ float g_z [900*8*48*48];
__device__ float g_cmax[8*48*48];
__device__ float g_csum[8*48*48];
__device__ float g_ao[48*900*256];
__device__ float g_t1[48*900*256];
__device__ float g_t2[48*900*256];
__device__ float g_t3[48*900*256];
__device__ float g_ff[48*900*1024];
__device__ float g_y [48*900];
__device__ __half g_a[99532800u];
__device__ __half g_b[2359296u];

__global__ void mma_gemm_k(const __half* A, const __half* B,
                           const float* bias, float* C, int M, int N, int K, int mode);
__global__ void act_h_k(const float* x, __half* out, unsigned n);
__global__ void w_h_k(const float* w, __half* out, int N, int K, int Kp);
__global__ void im2col1_h(const float* X, __half* out);
__global__ void im2col2_h(const float* in, __half* out);
__global__ void attn_scores_k(const float* Q, const float* Kb, const float* RW, float* Z);
__global__ void attn_scores_masked_k(const float* Q, const float* Kb, const float* RW,
                                     const float* L1w, const float* L1b,
                                     const float* L2w, const float* L2b, float* Z);
__global__ void col_max_k(const float* Z, float* cmax);
__global__ void col_expsum_k(float* Z, const float* cmax, float* csum);
__global__ void attn_out_k(const float* Z, const float* csum, const float* V, float* O);
__global__ void add_ln_k(const float* A, const float* B, float* O);
__global__ void outproj_k(const float* H, const float* w, const float* b, float* y);
__global__ void final_softmax_k(const float* y, float* out);

extern "C" void kernel_launch(void* const* d_in, const int* in_sizes, int n_in,
                              void* d_out, int out_size)
{
    const float* X_en = (const float*)d_in[0];
    const float* X_de = (const float*)d_in[1];
    const float* c1w = (const float*)d_in[2];
    const float* c1b = (const float*)d_in[3];
    const float* c2w = (const float*)d_in[4];
    const float* c2b = (const float*)d_in[5];
    const float* enc_wq = (const float*)d_in[6];
    const float* enc_wk = (const float*)d_in[7];
    const float* enc_wv = (const float*)d_in[8];
    const float* enc_rel = (const float*)d_in[9];
    const float* e_w1 = (const float*)d_in[10];
    const float* e_b1 = (const float*)d_in[11];
    const float* e_w2 = (const float*)d_in[12];
    const float* e_b2 = (const float*)d_in[13];
    const float* m_wq = (const float*)d_in[14];
    const float* m_wk = (const float*)d_in[15];
    const float* m_wv = (const float*)d_in[16];
    const float* m_rel = (const float*)d_in[17];
    const float* l1w = (const float*)d_in[18];
    const float* l1b = (const float*)d_in[19];
    const float* l2w = (const float*)d_in[20];
    const float* l2b = (const float*)d_in[21];
    const float* c_wq = (const float*)d_in[22];
    const float* c_wk = (const float*)d_in[23];
    const float* c_wv = (const float*)d_in[24];
    const float* c_rel = (const float*)d_in[25];
    const float* d_w1 = (const float*)d_in[26];
    const float* d_b1 = (const float*)d_in[27];
    const float* d_w2 = (const float*)d_in[28];
    const float* d_b2 = (const float*)d_in[29];
    const float* ow = (const float*)d_in[30];
    const float* ob = (const float*)d_in[31];

    float *c1, *xe, *xd, *q, *k, *v, *z, *cm, *cs, *ao, *t1, *t2, *t3, *ff, *yv;
    __half *ha, *hb;
    cudaGetSymbolAddress((void**)&c1, g_c1);
    cudaGetSymbolAddress((void**)&xe, g_xe);
    cudaGetSymbolAddress((void**)&xd, g_xd);
    cudaGetSymbolAddress((void**)&q,  g_q);
    cudaGetSymbolAddress((void**)&k,  g_k);
    cudaGetSymbolAddress((void**)&v,  g_v);
    cudaGetSymbolAddress((void**)&z,  g_z);
    cudaGetSymbolAddress((void**)&cm, g_cmax);
    cudaGetSymbolAddress((void**)&cs, g_csum);
    cudaGetSymbolAddress((void**)&ao, g_ao);
    cudaGetSymbolAddress((void**)&t1, g_t1);
    cudaGetSymbolAddress((void**)&t2, g_t2);
    cudaGetSymbolAddress((void**)&t3, g_t3);
    cudaGetSymbolAddress((void**)&ff, g_ff);
    cudaGetSymbolAddress((void**)&yv, g_y);
    cudaGetSymbolAddress((void**)&ha, g_a);
    cudaGetSymbolAddress((void**)&hb, g_b);

    cudaFuncSetAttribute(mma_gemm_k, cudaFuncAttributeMaxDynamicSharedMemorySize, 40960);

    const int M = 43200;
    const unsigned smem_bytes = 40960;
    dim3 agrid(900, 8);
    dim3 g256(2, 338);
    dim3 g1024(8, 338);
    const float* nobias = 0;

    w_h_k<<<320, 256>>>(c1w, hb, 256, 288, 320);
    im2col1_h<<<54000, 256>>>(X_en, ha);
    mma_gemm_k<<<g256, 256, smem_bytes>>>(ha, hb, c1b, c1, M, 256, 320, 2);
    w_h_k<<<2304, 256>>>(c2w, hb, 256, 2304, 2304);
    im2col2_h<<<388800, 256>>>(c1, ha);
    mma_gemm_k<<<g256, 256, smem_bytes>>>(ha, hb, c2b, xe, M, 256, 2304, 2);

    w_h_k<<<320, 256>>>(c1w, hb, 256, 288, 320);
    im2col1_h<<<54000, 256>>>(X_de, ha);
    mma_gemm_k<<<g256, 256, smem_bytes>>>(ha, hb, c1b, c1, M, 256, 320, 2);
    w_h_k<<<2304, 256>>>(c2w, hb, 256, 2304, 2304);
    im2col2_h<<<388800, 256>>>(c1, ha);
    mma_gemm_k<<<g256, 256, smem_bytes>>>(ha, hb, c2b, xd, M, 256, 2304, 2);

    act_h_k<<<43200, 256>>>(xe, ha, 11059200u);
    w_h_k<<<256, 256>>>(enc_wq, hb, 256, 256, 256);
    mma_gemm_k<<<g256, 256, smem_bytes>>>(ha, hb, nobias, q, M, 256, 256, 0);
    w_h_k<<<256, 256>>>(enc_wk, hb, 256, 256, 256);
    mma_gemm_k<<<g256, 256, smem_bytes>>>(ha, hb, nobias, k, M, 256, 256, 0);
    w_h_k<<<256, 256>>>(enc_wv, hb, 256, 256, 256);
    mma_gemm_k<<<g256, 256, smem_bytes>>>(ha, hb, nobias, v, M, 256, 256, 0);
    attn_scores_k<<<agrid, 256>>>(q, k, enc_rel, z);
    col_max_k<<<72, 256>>>(z, cm);
    col_expsum_k<<<72, 256>>>(z, cm, cs);
    attn_out_k<<<agrid, 256>>>(z, cs, v, ao);
    add_ln_k<<<43200, 256>>>(xe, ao, t1);
    act_h_k<<<43200, 256>>>(t1, ha, 11059200u);
    w_h_k<<<1024, 256>>>(e_w1, hb, 1024, 256, 256);
    mma_gemm_k<<<g1024, 256, smem_bytes>>>(ha, hb, e_b1, ff, M, 1024, 256, 1);
    act_h_k<<<172800, 256>>>(ff, ha, 44236800u);
    w_h_k<<<1024, 256>>>(e_w2, hb, 256, 1024, 1024);
    mma_gemm_k<<<g256, 256, smem_bytes>>>(ha, hb, e_b2, ao, M, 256, 1024, 0);
    add_ln_k<<<43200, 256>>>(t1, ao, t2);

    act_h_k<<<43200, 256>>>(xd, ha, 11059200u);
    w_h_k<<<256, 256>>>(m_wq, hb, 256, 256, 256);
    mma_gemm_k<<<g256, 256, smem_bytes>>>(ha, hb, nobias, q, M, 256, 256, 0);
    w_h_k<<<256, 256>>>(m_wk, hb, 256, 256, 256);
    mma_gemm_k<<<g256, 256, smem_bytes>>>(ha, hb, nobias, k, M, 256, 256, 0);
    w_h_k<<<256, 256>>>(m_wv, hb, 256, 256, 256);
    mma_gemm_k<<<g256, 256, smem_bytes>>>(ha, hb, nobias, v, M, 256, 256, 0);
    attn_scores_masked_k<<<agrid, 256>>>(q, k, m_rel, l1w, l1b, l2w, l2b, z);
    col_max_k<<<72, 256>>>(z, cm);
    col_expsum_k<<<72, 256>>>(z, cm, cs);
    attn_out_k<<<agrid, 256>>>(z, cs, v, ao);
    add_ln_k<<<43200, 256>>>(xd, ao, t1);

    act_h_k<<<43200, 256>>>(t1, ha, 11059200u);
    w_h_k<<<256, 256>>>(c_wq, hb, 256, 256, 256);
    mma_gemm_k<<<g256, 256, smem_bytes>>>(ha, hb, nobias, q, M, 256, 256, 0);
    act_h_k<<<43200, 256>>>(t2, ha, 11059200u);
    w_h_k<<<256, 256>>>(c_wk, hb, 256, 256, 256);
    mma_gemm_k<<<g256, 256, smem_bytes>>>(ha, hb, nobias, k, M, 256, 256, 0);
    w_h_k<<<256, 256>>>(c_wv, hb, 256, 256, 256);
    mma_gemm_k<<<g256, 256, smem_bytes>>>(ha, hb, nobias, v, M, 256, 256, 0);
    attn_scores_k<<<agrid, 256>>>(q, k, c_rel, z);
    col_max_k<<<72, 256>>>(z, cm);
    col_expsum_k<<<72, 256>>>(z, cm, cs);
    attn_out_k<<<agrid, 256>>>(z, cs, v, ao);
    add_ln_k<<<43200, 256>>>(ao, t1, t3);
    act_h_k<<<43200, 256>>>(t3, ha, 11059200u);
    w_h_k<<<1024, 256>>>(d_w1, hb, 1024, 256, 256);
    mma_gemm_k<<<g1024, 256, smem_bytes>>>(ha, hb, d_b1, ff, M, 1024, 256, 1);
    act_h_k<<<172800, 256>>>(ff, ha, 44236800u);
    w_h_k<<<1024, 256>>>(d_w2, hb, 256, 1024, 1024);
    mma_gemm_k<<<g256, 256, smem_bytes>>>(ha, hb, d_b2, ao, M, 256, 1024, 0);
    add_ln_k<<<43200, 256>>>(t3, ao, t1);

    outproj_k<<<5400, 256>>>(t1, ow, ob, yv);
    final_softmax_k<<<4, 256>>>(yv, (float*)d_out);
}

__device__ __forceinline__ unsigned smem_u32(const void* p)
{
    unsigned a;
    asm("{ .reg .u64 t; cvta.to.shared.u64 t, %1; cvt.u32.u64 %0, t; }" : "=r"(a) : "l"(p));
    return a;
}

__device__ __forceinline__ void mma16816(float* c, const unsigned* a, unsigned b0, unsigned b1)
{
    asm volatile("mma.sync.aligned.m16n8k16.row.col.f32.f16.f16.f32 {%0,%1,%2,%3}, {%4,%5,%6,%7}, {%8,%9}, {%0,%1,%2,%3};" : "+f"(c[0]), "+f"(c[1]), "+f"(c[2]), "+f"(c[3]) : "r"(a[0]), "r"(a[1]), "r"(a[2]), "r"(a[3]), "r"(b0), "r"(b1));
}

__device__ __forceinline__ void ldmx4(unsigned* r, unsigned addr)
{
    asm volatile("ldmatrix.sync.aligned.m8n8.x4.shared.b16 {%0,%1,%2,%3}, [%4];" : "=r"(r[0]), "=r"(r[1]), "=r"(r[2]), "=r"(r[3]) : "r"(addr));
}

__device__ __forceinline__ void stage_issue(
    const __half* A, const __half* B,
    unsigned st, int m0, int n0, int M, int K, int koff, int tid)
{
    for (int j = 0; j < 4; j++) {
        int i = tid + j * 256;
        int t = i >> 9;
        int r = (i >> 2) & 127;
        int c = i & 3;
        const __half* bp;
        int row;
        if (t == 0) {
            row = m0 + r;
            if (row >= M) row = M - 1;
            bp = A;
        } else {
            row = n0 + r;
            bp = B;
        }
        const __half* g = bp + (size_t)row * K + koff + c * 8;
        unsigned s = st + t * 10240 + r * 80 + c * 16;
        asm volatile("cp.async.ca.shared.global [%0], [%1], 16;" :: "r"(s), "l"(g) : "memory");
    }
    asm volatile("cp.async.commit_group;" ::: "memory");
}

__global__ __launch_bounds__(256, 2) void mma_gemm_k(
    const __half* A, const __half* B,
    const float* bias, float* C, int M, int N, int K, int mode)
{
    extern __shared__ char smem[];
    const int tid = threadIdx.x;
    const int m0 = blockIdx.y * 128;
    const int n0 = blockIdx.x * 128;
    const int warp = tid >> 5;
    const int lane = tid & 31;
    const int wm = warp & 3;
    const int wn = warp >> 2;
    const int gid = lane >> 2;
    const int tig = lane & 3;
    const unsigned sbase = smem_u32(smem);

    const int arow = wm * 32 + (lane & 15);
    const int acolb = ((lane >> 4) & 1) * 16;
    const int nrow = (lane & 7) + ((lane >> 4) & 1) * 8;
    const int bcolb = ((lane >> 3) & 1) * 16;

    float acc[2][8][4];
    for (int mf = 0; mf < 2; mf++)
        for (int nf = 0; nf < 8; nf++)
            for (int e = 0; e < 4; e++)
                acc[mf][nf][e] = 0.f;

    const int nk = K >> 5;
    stage_issue(A, B, sbase, m0, n0, M, K, 0, tid);

    for (int kb = 0; kb < nk; kb++) {
        if (kb + 1 < nk) {
            stage_issue(A, B, sbase + ((kb + 1) & 1) * 20480, m0, n0, M, K, (kb + 1) * 32, tid);
            asm volatile("cp.async.wait_group 1;" ::: "memory");
        } else {
            asm volatile("cp.async.wait_group 0;" ::: "memory");
        }
        __syncthreads();

        const unsigned st = sbase + (kb & 1) * 20480;
        for (int ks = 0; ks < 2; ks++) {
            const int kbyte = ks * 32;
            unsigned af[2][4];
            for (int mf = 0; mf < 2; mf++) {
                const unsigned arowoff = (unsigned)(arow + mf * 16) * 80u + kbyte + acolb;
                ldmx4(af[mf], st + arowoff);
            }
            for (int nfg = 0; nfg < 4; nfg++) {
                const unsigned browoff = (unsigned)(wn * 64 + nfg * 16 + nrow) * 80u + kbyte + bcolb;
                unsigned b4[4];
                ldmx4(b4, st + 10240u + browoff);
                for (int sub = 0; sub < 2; sub++) {
                    const int nf = nfg * 2 + sub;
                    for (int mf = 0; mf < 2; mf++) {
                        mma16816(acc[mf][nf], af[mf], b4[sub * 2], b4[sub * 2 + 1]);
                    }
                }
            }
        }
        __syncthreads();
    }

    for (int mf = 0; mf < 2; mf++) {
        for (int nf = 0; nf < 8; nf++) {
            const int col = n0 + wn * 64 + nf * 8 + tig * 2;
            float bv0 = 0.f;
            float bv1 = 0.f;
            if (bias) {
                bv0 = bias[col];
                bv1 = bias[col + 1];
            }
            for (int half2 = 0; half2 < 2; half2++) {
                const int m = m0 + wm * 32 + mf * 16 + gid + half2 * 8;
                if (m < M) {
                    float v0 = acc[mf][nf][half2 * 2 + 0] + bv0;
                    float v1 = acc[mf][nf][half2 * 2 + 1] + bv1;
                    if (mode == 1) {
                        v0 = fmaxf(v0, 0.f);
                        v1 = fmaxf(v1, 0.f);
                    }
                    if (mode == 2) {
                        const int b = m / 900;
                        const int p = m - b * 900;
                        float* ob = C + (size_t)b * 230400 + (size_t)col * 900 + p;
                        ob[0] = v0;
                        ob[900] = v1;
                    } else {
                        float2 stv;
                        stv.x = v0;
                        stv.y = v1;
                        *(float2*)(C + (size_t)m * N + col) = stv;
                    }
                }
            }
        }
    }
}

__global__ __launch_bounds__(256) void act_h_k(const float* x, __half* out, unsigned n)
{
    unsigned i = blockIdx.x * 256u + threadIdx.x;
    if (i >= n) return;
    out[i] = __float2half(x[i]);
}

__global__ __launch_bounds__(256) void w_h_k(const float* w, __half* out, int N, int K, int Kp)
{
    int i = blockIdx.x * 256 + threadIdx.x;
    if (i >= N * Kp) return;
    int r = i / Kp;
    int k = i - r * Kp;
    float v = 0.f;
    if (k < K) v = w[(size_t)r * K + k];
    out[i] = __float2half(v);
}

__global__ __launch_bounds__(256) void im2col1_h(const float* X, __half* out)
{
    unsigned i = blockIdx.x * 256u + threadIdx.x;
    if (i >= 13824000u) return;
    int m = (int)(i / 320u);
    int k = (int)(i - (unsigned)m * 320u);
    float v = 0.f;
    if (k < 288) {
        int ic = k / 9;
        int r9 = k - ic * 9;
        int ky = r9 / 3;
        int kx = r9 - ky * 3;
        int b = m / 900;
        int p = m - b * 900;
        int y = p / 30;
        int x = p - y * 30;
        v = X[((size_t)(b * 32 + ic) * 32 + (y + ky)) * 32 + (x + kx)];
    }
    out[i] = __float2half(v);
}

__global__ __launch_bounds__(256) void im2col2_h(const float* in, __half* out)
{
    unsigned i = blockIdx.x * 256u + threadIdx.x;
    if (i >= 99532800u) return;
    int m = (int)(i / 2304u);
    int k = (int)(i - (unsigned)m * 2304u);
    int ic = k / 9;
    int r9 = k - ic * 9;
    int ky = r9 / 3;
    int kx = r9 - ky * 3;
    int b = m / 900;
    int p = m - b * 900;
    int y = p / 30;
    int x = p - y * 30;
    int iy = y + ky - 1;
    int ix = x + kx - 1;
    float v = 0.f;
    if (iy >= 0 && iy < 30 && ix >= 0 && ix < 30) {
        v = in[(size_t)(b * 256 + ic) * 900 + iy * 30 + ix];
    }
    out[i] = __float2half(v);
}

__global__ __launch_bounds__(256) void attn_scores_k(
    const float* Q, const float* Kb, const float* RW, float* Z)
{
    const int s = blockIdx.x;
    const int h = blockIdx.y;
    const int tid = threadIdx.x;
    __shared__ float sq[48][33];
    __shared__ float sk[48][33];
    __shared__ float sw[32][49];
    __shared__ float se[48][49];
    for (int e = tid; e < 1536; e += 256) {
        int i = e >> 5;
        int d = e & 31;
        sq[i][d] = Q [((size_t)(s * 48 + i)) * 256 + h * 32 + d];
        sk[i][d] = Kb[((size_t)(s * 48 + i)) * 256 + h * 32 + d];
    }
    for (int e = tid; e < 1536; e += 256) {
        int d = e / 48;
        int j = e - d * 48;
        sw[d][j] = RW[(((size_t)s * 8 + h) * 32 + d) * 48 + j];
    }
    __syncthreads();
    float scv[9];
    for (int it = 0; it < 9; it++) {
        int e = tid + it * 256;
        int i = e / 48;
        int j = e - i * 48;
        float sc = 0.f;
        float em = 0.f;
        for (int d = 0; d < 32; d++) {
            float qv = sq[i][d];
            sc += qv * sk[j][d];
            em += qv * sw[d][j];
        }
        scv[it] = sc * 0.17677669529663689f;
        se[i][j] = em;
    }
    __syncthreads();
    size_t base = (size_t)s * 18432 + (size_t)h * 2304;
    for (int it = 0; it < 9; it++) {
        int e = tid + it * 256;
        int i = e / 48;
        int j = e - i * 48;
        float zz = scv[it];
        if (j <= i) zz += se[i][47 - i + j];
        Z[base + e] = zz;
    }
}

__global__ __launch_bounds__(256) void attn_scores_masked_k(
    const float* Q, const float* Kb, const float* RW,
    const float* L1w, const float* L1b,
    const float* L2w, const float* L2b, float* Z)
{
    const int s = blockIdx.x;
    const int h = blockIdx.y;
    const int tid = threadIdx.x;
    __shared__ float sq[48][33];
    __shared__ float sk[48][33];
    __shared__ float sw[32][49];
    __shared__ float se[48][49];
    __shared__ float ss[48][49];
    __shared__ float s1[48][49];
    for (int e = tid; e < 1536; e += 256) {
        int i = e >> 5;
        int d = e & 31;
        sq[i][d] = Q [((size_t)(s * 48 + i)) * 256 + h * 32 + d];
        sk[i][d] = Kb[((size_t)(s * 48 + i)) * 256 + h * 32 + d];
    }
    for (int e = tid; e < 1536; e += 256) {
        int d = e / 48;
        int j = e - d * 48;
        sw[d][j] = RW[(((size_t)s * 8 + h) * 32 + d) * 48 + j];
    }
    __syncthreads();
    for (int e = tid; e < 2304; e += 256) {
        int i = e / 48;
        int j = e - i * 48;
        float sc = 0.f;
        float em = 0.f;
        for (int d = 0; d < 32; d++) {
            float qv = sq[i][d];
            sc += qv * sk[j][d];
            em += qv * sw[d][j];
        }
        ss[i][j] = sc * 0.17677669529663689f;
        se[i][j] = em;
    }
    __syncthreads();
    for (int e = tid; e < 2304; e += 256) {
        int i = e / 48;
        int j = e - i * 48;
        float acc = L1b[j];
        for (int c = 0; c < 48; c++) acc += ss[i][c] * __ldg(&L1w[j * 48 + c]);
        s1[i][j] = acc;
    }
    __syncthreads();
    size_t base = (size_t)s * 18432 + (size_t)h * 2304;
    for (int e = tid; e < 2304; e += 256) {
        int a = e / 48;
        int b = e - a * 48;
        float acc = L2b[b];
        for (int c = 0; c < 48; c++) acc += s1[c][a] * __ldg(&L2w[b * 48 + c]);
        if (b > a) acc -= 3.402823466e+38f;
        if (b <= a) acc += se[a][47 - a + b];
        Z[base + e] = acc;
    }
}

__global__ __launch_bounds__(256) void col_max_k(const float* Z, float* cmax)
{
    int c = blockIdx.x * 256 + threadIdx.x;
    const float* p = Z + c;
    float m = -3.402823466e+38f;
    for (int s = 0; s < 900; s++) m = fmaxf(m, p[(size_t)s * 18432]);
    cmax[c] = m;
}

__global__ __launch_bounds__(256) void col_expsum_k(float* Z, const float* cmax, float* csum)
{
    int c = blockIdx.x * 256 + threadIdx.x;
    float m = cmax[c];
    float* p = Z + c;
    float sum = 0.f;
    for (int s = 0; s < 900; s++) {
        float v = __expf(p[(size_t)s * 18432] - m);
        p[(size_t)s * 18432] = v;
        sum += v;
    }
    csum[c] = sum;
}

__global__ __launch_bounds__(256) void attn_out_k(
    const float* Z, const float* csum, const float* V, float* O)
{
    const int s = blockIdx.x;
    const int h = blockIdx.y;
    const int tid = threadIdx.x;
    __shared__ float sp[48][49];
    __shared__ float sv[48][33];
    size_t base = (size_t)s * 18432 + (size_t)h * 2304;
    for (int e = tid; e < 2304; e += 256) {
        int i = e / 48;
        int j = e - i * 48;
        sp[i][j] = Z[base + e] / csum[h * 2304 + e];
    }
    for (int e = tid; e < 1536; e += 256) {
        int j = e >> 5;
        int d = e & 31;
        sv[j][d] = V[((size_t)(s * 48 + j)) * 256 + h * 32 + d];
    }
    __syncthreads();
    for (int e = tid; e < 1536; e += 256) {
        int i = e >> 5;
        int d = e & 31;
        float acc = 0.f;
        for (int j = 0; j < 48; j++) acc += sp[i][j] * sv[j][d];
        O[(size_t)((s * 8 + h) * 48 + i) * 32 + d] = acc;
    }
}

__device__ __forceinline__ float block_sum256(float v, float* sbuf)
{
    for (int o = 16; o > 0; o >>= 1) v += __shfl_down_sync(0xffffffffu, v, o);
    int w = threadIdx.x >> 5;
    int l = threadIdx.x & 31;
    if (l == 0) sbuf[w] = v;
    __syncthreads();
    if (w == 0) {
        v = (l < 8) ? sbuf[l] : 0.f;
        for (int o = 4; o > 0; o >>= 1) v += __shfl_down_sync(0xffffffffu, v, o);
        if (l == 0) sbuf[0] = v;
    }
    __syncthreads();
    float r = sbuf[0];
    __syncthreads();
    return r;
}

__global__ __launch_bounds__(256) void add_ln_k(const float* A, const float* B, float* O)
{
    __shared__ float sbuf[8];
    size_t base = (size_t)blockIdx.x * 256;
    float v = A[base + threadIdx.x] + B[base + threadIdx.x];
    float mean = block_sum256(v, sbuf) * (1.f / 256.f);
    float d = v - mean;
    float var = block_sum256(d * d, sbuf) * (1.f / 256.f);
    O[base + threadIdx.x] = d * rsqrtf(var + 1e-5f);
}

__global__ __launch_bounds__(256) void outproj_k(const float* H, const float* w,
                                                 const float* b, float* y)
{
    int warp = (blockIdx.x * 256 + threadIdx.x) >> 5;
    int lane = threadIdx.x & 31;
    if (warp >= 43200) return;
    const float* row = H + (size_t)warp * 256;
    float s = 0.f;
    for (int k = lane; k < 256; k += 32) s += row[k] * w[k];
    for (int o = 16; o > 0; o >>= 1) s += __shfl_down_sync(0xffffffffu, s, o);
    if (lane == 0) y[warp] = s + b[0];
}

__global__ __launch_bounds__(256) void final_softmax_k(const float* y, float* out)
{
    int s = blockIdx.x * 256 + threadIdx.x;
    if (s >= 900) return;
    float m = -3.402823466e+38f;
    for (int b = 0; b < 48; b++) m = fmaxf(m, y[b * 900 + s]);
    float sum = 0.f;
    for (int b = 0; b < 48; b++) sum += __expf(y[b * 900 + s] - m);
    float inv = 1.f / sum;
    for (int b = 0; b < 48; b++) out[b * 900 + s] = __expf(y[b * 900 + s] - m) * inv;
}

// round 13
// speedup vs baseline: 1.2671x; 1.0059x over previous
#include <cuda_runtime.h>
#include <cuda_fp16.h>
#include <cstdint>
#include <math.h>

__device__ float g_c1[48*256*900];
__device__ float g_xe[48*256*900];
__device__ float g_xd[48*256*900];
__device__ float g_q [48*900*256];
__device__ float g_k [48*900*256];
__device__ float g_v [48*900*256];
__device__ float g_z [900*8*48*48];
__device__ float g_cmax[8*48*48];
__device__ float g_csum[8*48*48];
__device__ float g_ao[48*900*256];
__device__ float g_t1[48*900*256];
__device__ float g_t2[48*900*256];
__device__ float g_t3[48*900*256];
__device__ float g_ff[48*900*1024];
__device__ float g_y [48*900];
__device__ __half g_a[99532800u];
__device__ __half g_b[2359296u];

__global__ void mma_gemm_k(const __half* A, const __half* B,
                           const float* bias, float* C, int M, int N, int K, int mode);
__global__ void act_h_k(const float* x, __half* out, unsigned n);
__global__ void w_h_k(const float* w, __half* out, int N, int K, int Kp);
__global__ void im2col1_h(const float* X, __half* out);
__global__ void im2col2_h(const float* in, __half* out);
__global__ void attn_scores_k(const float* Q, const float* Kb, const float* RW, float* Z);
__global__ void attn_scores_masked_k(const float* Q, const float* Kb, const float* RW,
                                     const float* L1w, const float* L1b,
                                     const float* L2w, const float* L2b, float* Z);
__global__ void col_max_k(const float* Z, float* cmax);
__global__ void col_expsum_k(float* Z, const float* cmax, float* csum);
__global__ void attn_out_k(const float* Z, const float* csum, const float* V, float* O);
__global__ void add_ln_k(const float* A, const float* B, float* O);
__global__ void outproj_k(const float* H, const float* w, const float* b, float* y);
__global__ void final_softmax_k(const float* y, float* out);

extern "C" void kernel_launch(void* const* d_in, const int* in_sizes, int n_in,
                              void* d_out, int out_size)
{
    const float* X_en = (const float*)d_in[0];
    const float* X_de = (const float*)d_in[1];
    const float* c1w = (const float*)d_in[2];
    const float* c1b = (const float*)d_in[3];
    const float* c2w = (const float*)d_in[4];
    const float* c2b = (const float*)d_in[5];
    const float* enc_wq = (const float*)d_in[6];
    const float* enc_wk = (const float*)d_in[7];
    const float* enc_wv = (const float*)d_in[8];
    const float* enc_rel = (const float*)d_in[9];
    const float* e_w1 = (const float*)d_in[10];
    const float* e_b1 = (const float*)d_in[11];
    const float* e_w2 = (const float*)d_in[12];
    const float* e_b2 = (const float*)d_in[13];
    const float* m_wq = (const float*)d_in[14];
    const float* m_wk = (const float*)d_in[15];
    const float* m_wv = (const float*)d_in[16];
    const float* m_rel = (const float*)d_in[17];
    const float* l1w = (const float*)d_in[18];
    const float* l1b = (const float*)d_in[19];
    const float* l2w = (const float*)d_in[20];
    const float* l2b = (const float*)d_in[21];
    const float* c_wq = (const float*)d_in[22];
    const float* c_wk = (const float*)d_in[23];
    const float* c_wv = (const float*)d_in[24];
    const float* c_rel = (const float*)d_in[25];
    const float* d_w1 = (const float*)d_in[26];
    const float* d_b1 = (const float*)d_in[27];
    const float* d_w2 = (const float*)d_in[28];
    const float* d_b2 = (const float*)d_in[29];
    const float* ow = (const float*)d_in[30];
    const float* ob = (const float*)d_in[31];

    float *c1, *xe, *xd, *q, *k, *v, *z, *cm, *cs, *ao, *t1, *t2, *t3, *ff, *yv;
    __half *ha, *hb;
    cudaGetSymbolAddress((void**)&c1, g_c1);
    cudaGetSymbolAddress((void**)&xe, g_xe);
    cudaGetSymbolAddress((void**)&xd, g_xd);
    cudaGetSymbolAddress((void**)&q,  g_q);
    cudaGetSymbolAddress((void**)&k,  g_k);
    cudaGetSymbolAddress((void**)&v,  g_v);
    cudaGetSymbolAddress((void**)&z,  g_z);
    cudaGetSymbolAddress((void**)&cm, g_cmax);
    cudaGetSymbolAddress((void**)&cs, g_csum);
    cudaGetSymbolAddress((void**)&ao, g_ao);
    cudaGetSymbolAddress((void**)&t1, g_t1);
    cudaGetSymbolAddress((void**)&t2, g_t2);
    cudaGetSymbolAddress((void**)&t3, g_t3);
    cudaGetSymbolAddress((void**)&ff, g_ff);
    cudaGetSymbolAddress((void**)&yv, g_y);
    cudaGetSymbolAddress((void**)&ha, g_a);
    cudaGetSymbolAddress((void**)&hb, g_b);

    cudaFuncSetAttribute(mma_gemm_k, cudaFuncAttributeMaxDynamicSharedMemorySize, 81920);

    const int M = 43200;
    const unsigned smem_bytes = 81920;
    dim3 agrid(900, 8);
    dim3 g256(2, 338);
    dim3 g1024(8, 338);
    const float* nobias = 0;

    w_h_k<<<320, 256>>>(c1w, hb, 256, 288, 320);
    im2col1_h<<<54000, 256>>>(X_en, ha);
    mma_gemm_k<<<g256, 256, smem_bytes>>>(ha, hb, c1b, c1, M, 256, 320, 2);
    w_h_k<<<2304, 256>>>(c2w, hb, 256, 2304, 2304);
    im2col2_h<<<388800, 256>>>(c1, ha);
    mma_gemm_k<<<g256, 256, smem_bytes>>>(ha, hb, c2b, xe, M, 256, 2304, 2);

    w_h_k<<<320, 256>>>(c1w, hb, 256, 288, 320);
    im2col1_h<<<54000, 256>>>(X_de, ha);
    mma_gemm_k<<<g256, 256, smem_bytes>>>(ha, hb, c1b, c1, M, 256, 320, 2);
    w_h_k<<<2304, 256>>>(c2w, hb, 256, 2304, 2304);
    im2col2_h<<<388800, 256>>>(c1, ha);
    mma_gemm_k<<<g256, 256, smem_bytes>>>(ha, hb, c2b, xd, M, 256, 2304, 2);

    act_h_k<<<43200, 256>>>(xe, ha, 11059200u);
    w_h_k<<<256, 256>>>(enc_wq, hb, 256, 256, 256);
    mma_gemm_k<<<g256, 256, smem_bytes>>>(ha, hb, nobias, q, M, 256, 256, 0);
    w_h_k<<<256, 256>>>(enc_wk, hb, 256, 256, 256);
    mma_gemm_k<<<g256, 256, smem_bytes>>>(ha, hb, nobias, k, M, 256, 256, 0);
    w_h_k<<<256, 256>>>(enc_wv, hb, 256, 256, 256);
    mma_gemm_k<<<g256, 256, smem_bytes>>>(ha, hb, nobias, v, M, 256, 256, 0);
    attn_scores_k<<<agrid, 256>>>(q, k, enc_rel, z);
    col_max_k<<<72, 256>>>(z, cm);
    col_expsum_k<<<72, 256>>>(z, cm, cs);
    attn_out_k<<<agrid, 256>>>(z, cs, v, ao);
    add_ln_k<<<43200, 256>>>(xe, ao, t1);
    act_h_k<<<43200, 256>>>(t1, ha, 11059200u);
    w_h_k<<<1024, 256>>>(e_w1, hb, 1024, 256, 256);
    mma_gemm_k<<<g1024, 256, smem_bytes>>>(ha, hb, e_b1, ff, M, 1024, 256, 1);
    act_h_k<<<172800, 256>>>(ff, ha, 44236800u);
    w_h_k<<<1024, 256>>>(e_w2, hb, 256, 1024, 1024);
    mma_gemm_k<<<g256, 256, smem_bytes>>>(ha, hb, e_b2, ao, M, 256, 1024, 0);
    add_ln_k<<<43200, 256>>>(t1, ao, t2);

    act_h_k<<<43200, 256>>>(xd, ha, 11059200u);
    w_h_k<<<256, 256>>>(m_wq, hb, 256, 256, 256);
    mma_gemm_k<<<g256, 256, smem_bytes>>>(ha, hb, nobias, q, M, 256, 256, 0);
    w_h_k<<<256, 256>>>(m_wk, hb, 256, 256, 256);
    mma_gemm_k<<<g256, 256, smem_bytes>>>(ha, hb, nobias, k, M, 256, 256, 0);
    w_h_k<<<256, 256>>>(m_wv, hb, 256, 256, 256);
    mma_gemm_k<<<g256, 256, smem_bytes>>>(ha, hb, nobias, v, M, 256, 256, 0);
    attn_scores_masked_k<<<agrid, 256>>>(q, k, m_rel, l1w, l1b, l2w, l2b, z);
    col_max_k<<<72, 256>>>(z, cm);
    col_expsum_k<<<72, 256>>>(z, cm, cs);
    attn_out_k<<<agrid, 256>>>(z, cs, v, ao);
    add_ln_k<<<43200, 256>>>(xd, ao, t1);

    act_h_k<<<43200, 256>>>(t1, ha, 11059200u);
    w_h_k<<<256, 256>>>(c_wq, hb, 256, 256, 256);
    mma_gemm_k<<<g256, 256, smem_bytes>>>(ha, hb, nobias, q, M, 256, 256, 0);
    act_h_k<<<43200, 256>>>(t2, ha, 11059200u);
    w_h_k<<<256, 256>>>(c_wk, hb, 256, 256, 256);
    mma_gemm_k<<<g256, 256, smem_bytes>>>(ha, hb, nobias, k, M, 256, 256, 0);
    w_h_k<<<256, 256>>>(c_wv, hb, 256, 256, 256);
    mma_gemm_k<<<g256, 256, smem_bytes>>>(ha, hb, nobias, v, M, 256, 256, 0);
    attn_scores_k<<<agrid, 256>>>(q, k, c_rel, z);
    col_max_k<<<72, 256>>>(z, cm);
    col_expsum_k<<<72, 256>>>(z, cm, cs);
    attn_out_k<<<agrid, 256>>>(z, cs, v, ao);
    add_ln_k<<<43200, 256>>>(ao, t1, t3);
    act_h_k<<<43200, 256>>>(t3, ha, 11059200u);
    w_h_k<<<1024, 256>>>(d_w1, hb, 1024, 256, 256);
    mma_gemm_k<<<g1024, 256, smem_bytes>>>(ha, hb, d_b1, ff, M, 1024, 256, 1);
    act_h_k<<<172800, 256>>>(ff, ha, 44236800u);
    w_h_k<<<1024, 256>>>(d_w2, hb, 256, 1024, 1024);
    mma_gemm_k<<<g256, 256, smem_bytes>>>(ha, hb, d_b2, ao, M, 256, 1024, 0);
    add_ln_k<<<43200, 256>>>(t3, ao, t1);

    outproj_k<<<5400, 256>>>(t1, ow, ob, yv);
    final_softmax_k<<<4, 256>>>(yv, (float*)d_out);
}

__device__ __forceinline__ unsigned smem_u32(const void* p)
{
    unsigned a;
    asm("{ .reg .u64 t; cvta.to.shared.u64 t, %1; cvt.u32.u64 %0, t; }" : "=r"(a) : "l"(p));
    return a;
}

__device__ __forceinline__ void mma16816(float* c, const unsigned* a, unsigned b0, unsigned b1)
{
    asm volatile("mma.sync.aligned.m16n8k16.row.col.f32.f16.f16.f32 {%0,%1,%2,%3}, {%4,%5,%6,%7}, {%8,%9}, {%0,%1,%2,%3};" : "+f"(c[0]), "+f"(c[1]), "+f"(c[2]), "+f"(c[3]) : "r"(a[0]), "r"(a[1]), "r"(a[2]), "r"(a[3]), "r"(b0), "r"(b1));
}

__device__ __forceinline__ void ldmx4(unsigned* r, unsigned addr)
{
    asm volatile("ldmatrix.sync.aligned.m8n8.x4.shared.b16 {%0,%1,%2,%3}, [%4];" : "=r"(r[0]), "=r"(r[1]), "=r"(r[2]), "=r"(r[3]) : "r"(addr));
}

__device__ __forceinline__ void stage_issue(
    const __half* A, const __half* B,
    unsigned st, int m0, int n0, int M, int K, int koff, int tid)
{
    for (int j = 0; j < 4; j++) {
        int i = tid + j * 256;
        int t = i >> 9;
        int r = (i >> 2) & 127;
        int c = i & 3;
        const __half* bp;
        int row;
        if (t == 0) {
            row = m0 + r;
            if (row >= M) row = M - 1;
            bp = A;
        } else {
            row = n0 + r;
            bp = B;
        }
        const __half* g = bp + (size_t)row * K + koff + c * 8;
        unsigned s = st + t * 10240 + r * 80 + c * 16;
        asm volatile("cp.async.ca.shared.global [%0], [%1], 16;" :: "r"(s), "l"(g) : "memory");
    }
    asm volatile("cp.async.commit_group;" ::: "memory");
}

__global__ __launch_bounds__(256, 2) void mma_gemm_k(
    const __half* A, const __half* B,
    const float* bias, float* C, int M, int N, int K, int mode)
{
    extern __shared__ char smem[];
    const int tid = threadIdx.x;
    const int m0 = blockIdx.y * 128;
    const int n0 = blockIdx.x * 128;
    const int warp = tid >> 5;
    const int lane = tid & 31;
    const int wm = warp & 3;
    const int wn = warp >> 2;
    const int gid = lane >> 2;
    const int tig = lane & 3;
    const unsigned sbase = smem_u32(smem);

    const int arow = wm * 32 + (lane & 15);
    const int acolb = ((lane >> 4) & 1) * 16;
    const int nrow = (lane & 7) + ((lane >> 4) & 1) * 8;
    const int bcolb = ((lane >> 3) & 1) * 16;

    float acc[2][8][4];
    for (int mf = 0; mf < 2; mf++)
        for (int nf = 0; nf < 8; nf++)
            for (int e = 0; e < 4; e++)
                acc[mf][nf][e] = 0.f;

    const int nk = K >> 5;
    int pre = nk < 3 ? nk : 3;
    for (int i = 0; i < pre; i++) {
        stage_issue(A, B, sbase + (unsigned)(i & 3) * 20480u, m0, n0, M, K, i * 32, tid);
    }

    for (int kb = 0; kb < nk; kb++) {
        int pending = nk - kb;
        if (pending > 3) pending = 3;
        if (pending == 3) {
            asm volatile("cp.async.wait_group 2;" ::: "memory");
        } else if (pending == 2) {
            asm volatile("cp.async.wait_group 1;" ::: "memory");
        } else {
            asm volatile("cp.async.wait_group 0;" ::: "memory");
        }
        __syncthreads();

        const unsigned st = sbase + (unsigned)(kb & 3) * 20480u;
        for (int ks = 0; ks < 2; ks++) {
            const int kbyte = ks * 32;
            unsigned af[2][4];
            for (int mf = 0; mf < 2; mf++) {
                const unsigned arowoff = (unsigned)(arow + mf * 16) * 80u + kbyte + acolb;
                ldmx4(af[mf], st + arowoff);
            }
            for (int nfg = 0; nfg < 4; nfg++) {
                const unsigned browoff = (unsigned)(wn * 64 + nfg * 16 + nrow) * 80u + kbyte + bcolb;
                unsigned b4[4];
                ldmx4(b4, st + 10240u + browoff);
                for (int sub = 0; sub < 2; sub++) {
                    const int nf = nfg * 2 + sub;
                    for (int mf = 0; mf < 2; mf++) {
                        mma16816(acc[mf][nf], af[mf], b4[sub * 2], b4[sub * 2 + 1]);
                    }
                }
            }
        }
        if (kb + 3 < nk) {
            stage_issue(A, B, sbase + (unsigned)((kb + 3) & 3) * 20480u, m0, n0, M, K, (kb + 3) * 32, tid);
        }
    }

    for (int mf = 0; mf < 2; mf++) {
        for (int nf = 0; nf < 8; nf++) {
            const int col = n0 + wn * 64 + nf * 8 + tig * 2;
            float bv0 = 0.f;
            float bv1 = 0.f;
            if (bias) {
                bv0 = bias[col];
                bv1 = bias[col + 1];
            }
            for (int half2 = 0; half2 < 2; half2++) {
                const int m = m0 + wm * 32 + mf * 16 + gid + half2 * 8;
                if (m < M) {
                    float v0 = acc[mf][nf][half2 * 2 + 0] + bv0;
                    float v1 = acc[mf][nf][half2 * 2 + 1] + bv1;
                    if (mode == 1) {
                        v0 = fmaxf(v0, 0.f);
                        v1 = fmaxf(v1, 0.f);
                    }
                    if (mode == 2) {
                        const int b = m / 900;
                        const int p = m - b * 900;
                        float* ob = C + (size_t)b * 230400 + (size_t)col * 900 + p;
                        ob[0] = v0;
                        ob[900] = v1;
                    } else {
                        float2 stv;
                        stv.x = v0;
                        stv.y = v1;
                        *(float2*)(C + (size_t)m * N + col) = stv;
                    }
                }
            }
        }
    }
}

__global__ __launch_bounds__(256) void act_h_k(const float* x, __half* out, unsigned n)
{
    unsigned i = blockIdx.x * 256u + threadIdx.x;
    if (i >= n) return;
    out[i] = __float2half(x[i]);
}

__global__ __launch_bounds__(256) void w_h_k(const float* w, __half* out, int N, int K, int Kp)
{
    int i = blockIdx.x * 256 + threadIdx.x;
    if (i >= N * Kp) return;
    int r = i / Kp;
    int k = i - r * Kp;
    float v = 0.f;
    if (k < K) v = w[(size_t)r * K + k];
    out[i] = __float2half(v);
}

__global__ __launch_bounds__(256) void im2col1_h(const float* X, __half* out)
{
    unsigned i = blockIdx.x * 256u + threadIdx.x;
    if (i >= 13824000u) return;
    int m = (int)(i / 320u);
    int k = (int)(i - (unsigned)m * 320u);
    float v = 0.f;
    if (k < 288) {
        int ic = k / 9;
        int r9 = k - ic * 9;
        int ky = r9 / 3;
        int kx = r9 - ky * 3;
        int b = m / 900;
        int p = m - b * 900;
        int y = p / 30;
        int x = p - y * 30;
        v = X[((size_t)(b * 32 + ic) * 32 + (y + ky)) * 32 + (x + kx)];
    }
    out[i] = __float2half(v);
}

__global__ __launch_bounds__(256) void im2col2_h(const float* in, __half* out)
{
    unsigned i = blockIdx.x * 256u + threadIdx.x;
    if (i >= 99532800u) return;
    int m = (int)(i / 2304u);
    int k = (int)(i - (unsigned)m * 2304u);
    int ic = k / 9;
    int r9 = k - ic * 9;
    int ky = r9 / 3;
    int kx = r9 - ky * 3;
    int b = m / 900;
    int p = m - b * 900;
    int y = p / 30;
    int x = p - y * 30;
    int iy = y + ky - 1;
    int ix = x + kx - 1;
    float v = 0.f;
    if (iy >= 0 && iy < 30 && ix >= 0 && ix < 30) {
        v = in[(size_t)(b * 256 + ic) * 900 + iy * 30 + ix];
    }
    out[i] = __float2half(v);
}

__global__ __launch_bounds__(256) void attn_scores_k(
    const float* Q, const float* Kb, const float* RW, float* Z)
{
    const int s = blockIdx.x;
    const int h = blockIdx.y;
    const int tid = threadIdx.x;
    __shared__ float sq[48][33];
    __shared__ float sk[48][33];
    __shared__ float sw[32][49];
    __shared__ float se[48][49];
    for (int e = tid; e < 1536; e += 256) {
        int i = e >> 5;
        int d = e & 31;
        sq[i][d] = Q [((size_t)(s * 48 + i)) * 256 + h * 32 + d];
        sk[i][d] = Kb[((size_t)(s * 48 + i)) * 256 + h * 32 + d];
    }
    for (int e = tid; e < 1536; e += 256) {
        int d = e / 48;
        int j = e - d * 48;
        sw[d][j] = RW[(((size_t)s * 8 + h) * 32 + d) * 48 + j];
    }
    __syncthreads();
    float scv[9];
    for (int it = 0; it < 9; it++) {
        int e = tid + it * 256;
        int i = e / 48;
        int j = e - i * 48;
        float sc = 0.f;
        float em = 0.f;
        for (int d = 0; d < 32; d++) {
            float qv = sq[i][d];
            sc += qv * sk[j][d];
            em += qv * sw[d][j];
        }
        scv[it] = sc * 0.17677669529663689f;
        se[i][j] = em;
    }
    __syncthreads();
    size_t base = (size_t)s * 18432 + (size_t)h * 2304;
    for (int it = 0; it < 9; it++) {
        int e = tid + it * 256;
        int i = e / 48;
        int j = e - i * 48;
        float zz = scv[it];
        if (j <= i) zz += se[i][47 - i + j];
        Z[base + e] = zz;
    }
}

__global__ __launch_bounds__(256) void attn_scores_masked_k(
    const float* Q, const float* Kb, const float* RW,
    const float* L1w, const float* L1b,
    const float* L2w, const float* L2b, float* Z)
{
    const int s = blockIdx.x;
    const int h = blockIdx.y;
    const int tid = threadIdx.x;
    __shared__ float sq[48][33];
    __shared__ float sk[48][33];
    __shared__ float sw[32][49];
    __shared__ float se[48][49];
    __shared__ float ss[48][49];
    __shared__ float s1[48][49];
    for (int e = tid; e < 1536; e += 256) {
        int i = e >> 5;
        int d = e & 31;
        sq[i][d] = Q [((size_t)(s * 48 + i)) * 256 + h * 32 + d];
        sk[i][d] = Kb[((size_t)(s * 48 + i)) * 256 + h * 32 + d];
    }
    for (int e = tid; e < 1536; e += 256) {
        int d = e / 48;
        int j = e - d * 48;
        sw[d][j] = RW[(((size_t)s * 8 + h) * 32 + d) * 48 + j];
    }
    __syncthreads();
    for (int e = tid; e < 2304; e += 256) {
        int i = e / 48;
        int j = e - i * 48;
        float sc = 0.f;
        float em = 0.f;
        for (int d = 0; d < 32; d++) {
            float qv = sq[i][d];
            sc += qv * sk[j][d];
            em += qv * sw[d][j];
        }
        ss[i][j] = sc * 0.17677669529663689f;
        se[i][j] = em;
    }
    __syncthreads();
    for (int e = tid; e < 2304; e += 256) {
        int i = e / 48;
        int j = e - i * 48;
        float acc = L1b[j];
        for (int c = 0; c < 48; c++) acc += ss[i][c] * __ldg(&L1w[j * 48 + c]);
        s1[i][j] = acc;
    }
    __syncthreads();
    size_t base = (size_t)s * 18432 + (size_t)h * 2304;
    for (int e = tid; e < 2304; e += 256) {
        int a = e / 48;
        int b = e - a * 48;
        float acc = L2b[b];
        for (int c = 0; c < 48; c++) acc += s1[c][a] * __ldg(&L2w[b * 48 + c]);
        if (b > a) acc -= 3.402823466e+38f;
        if (b <= a) acc += se[a][47 - a + b];
        Z[base + e] = acc;
    }
}

__global__ __launch_bounds__(256) void col_max_k(const float* Z, float* cmax)
{
    int c = blockIdx.x * 256 + threadIdx.x;
    const float* p = Z + c;
    float m = -3.402823466e+38f;
    for (int s = 0; s < 900; s++) m = fmaxf(m, p[(size_t)s * 18432]);
    cmax[c] = m;
}

__global__ __launch_bounds__(256) void col_expsum_k(float* Z, const float* cmax, float* csum)
{
    int c = blockIdx.x * 256 + threadIdx.x;
    float m = cmax[c];
    float* p = Z + c;
    float sum = 0.f;
    for (int s = 0; s < 900; s++) {
        float v = __expf(p[(size_t)s * 18432] - m);
        p[(size_t)s * 18432] = v;
        sum += v;
    }
    csum[c] = sum;
}

__global__ __launch_bounds__(256) void attn_out_k(
    const float* Z, const float* csum, const float* V, float* O)
{
    const int s = blockIdx.x;
    const int h = blockIdx.y;
    const int tid = threadIdx.x;
    __shared__ float sp[48][49];
    __shared__ float sv[48][33];
    size_t base = (size_t)s * 18432 + (size_t)h * 2304;
    for (int e = tid; e < 2304; e += 256) {
        int i = e / 48;
        int j = e - i * 48;
        sp[i][j] = Z[base + e] / csum[h * 2304 + e];
    }
    for (int e = tid; e < 1536; e += 256) {
        int j = e >> 5;
        int d = e & 31;
        sv[j][d] = V[((size_t)(s * 48 + j)) * 256 + h * 32 + d];
    }
    __syncthreads();
    for (int e = tid; e < 1536; e += 256) {
        int i = e >> 5;
        int d = e & 31;
        float acc = 0.f;
        for (int j = 0; j < 48; j++) acc += sp[i][j] * sv[j][d];
        O[(size_t)((s * 8 + h) * 48 + i) * 32 + d] = acc;
    }
}

__device__ __forceinline__ float block_sum256(float v, float* sbuf)
{
    for (int o = 16; o > 0; o >>= 1) v += __shfl_down_sync(0xffffffffu, v, o);
    int w = threadIdx.x >> 5;
    int l = threadIdx.x & 31;
    if (l == 0) sbuf[w] = v;
    __syncthreads();
    if (w == 0) {
        v = (l < 8) ? sbuf[l] : 0.f;
        for (int o = 4; o > 0; o >>= 1) v += __shfl_down_sync(0xffffffffu, v, o);
        if (l == 0) sbuf[0] = v;
    }
    __syncthreads();
    float r = sbuf[0];
    __syncthreads();
    return r;
}

__global__ __launch_bounds__(256) void add_ln_k(const float* A, const float* B, float* O)
{
    __shared__ float sbuf[8];
    size_t base = (size_t)blockIdx.x * 256;
    float v = A[base + threadIdx.x] + B[base + threadIdx.x];
    float mean = block_sum256(v, sbuf) * (1.f / 256.f);
    float d = v - mean;
    float var = block_sum256(d * d, sbuf) * (1.f / 256.f);
    O[base + threadIdx.x] = d * rsqrtf(var + 1e-5f);
}

__global__ __launch_bounds__(256) void outproj_k(const float* H, const float* w,
                                                 const float* b, float* y)
{
    int warp = (blockIdx.x * 256 + threadIdx.x) >> 5;
    int lane = threadIdx.x & 31;
    if (warp >= 43200) return;
    const float* row = H + (size_t)warp * 256;
    float s = 0.f;
    for (int k = lane; k < 256; k += 32) s += row[k] * w[k];
    for (int o = 16; o > 0; o >>= 1) s += __shfl_down_sync(0xffffffffu, s, o);
    if (lane == 0) y[warp] = s + b[0];
}

__global__ __launch_bounds__(256) void final_softmax_k(const float* y, float* out)
{
    int s = blockIdx.x * 256 + threadIdx.x;
    if (s >= 900) return;
    float m = -3.402823466e+38f;
    for (int b = 0; b < 48; b++) m = fmaxf(m, y[b * 900 + s]);
    float sum = 0.f;
    for (int b = 0; b < 48; b++) sum += __expf(y[b * 900 + s] - m);
    float inv = 1.f / sum;
    for (int b = 0; b < 48; b++) out[b * 900 + s] = __expf(y[b * 900 + s] - m) * inv;
}

// round 15
// speedup vs baseline: 1.3198x; 1.0416x over previous
#include <cuda_runtime.h>
#include <cuda_fp16.h>
#include <cstdint>
#include <math.h>

__device__ float g_c1[48*256*900];
__device__ float g_xe[48*256*900];
__device__ float g_xd[48*256*900];
__device__ float g_q [48*900*768];
__device__ float g_k [48*900*512];
__device__ float g_z [900*8*48*48];
__device__ float g_cmax[8*48*48];
__device__ float g_csum[8*48*48];
__device__ float g_ao[48*900*256];
__device__ float g_t1[48*900*256];
__device__ float g_t2[48*900*256];
__device__ float g_t3[48*900*256];
__device__ float g_y [48*900];
__device__ __half g_a[99532800u];
__device__ __half g_b[2359296u];
__device__ __half g_xeh[11059200u];
__device__ __half g_xdh[11059200u];
__device__ __half g_t1h[11059200u];
__device__ __half g_t2h[11059200u];
__device__ __half g_t3h[11059200u];

__global__ void mma_gemm_k(const __half* A, const __half* B,
                           const float* bias, float* C, __half* H,
                           int M, int N, int K, int mode);
__global__ void w_h_k(const float* w, __half* out, int N, int K, int Kp);
__global__ void im2col1_h(const float* X, __half* out);
__global__ void im2col2_h(const float* in, __half* out);
__global__ void attn_scores_k(const float* Q, const float* Kb, const float* RW, float* Z,
                              int qs, int ks);
__global__ void attn_scores_masked_k(const float* Q, const float* Kb, const float* RW,
                                     const float* L1w, const float* L1b,
                                     const float* L2w, const float* L2b, float* Z,
                                     int qs, int ks);
__global__ void col_max_k(const float* Z, float* cmax);
__global__ void col_expsum_k(float* Z, const float* cmax, float* csum);
__global__ void attn_out_k(const float* Z, const float* csum, const float* V, float* O, int vs);
__global__ void add_ln_k(const float* A, const float* B, float* O, __half* H);
__global__ void outproj_k(const float* H, const float* w, const float* b, float* y);
__global__ void final_softmax_k(const float* y, float* out);

extern "C" void kernel_launch(void* const* d_in, const int* in_sizes, int n_in,
                              void* d_out, int out_size)
{
    const float* X_en = (const float*)d_in[0];
    const float* X_de = (const float*)d_in[1];
    const float* c1w = (const float*)d_in[2];
    const float* c1b = (const float*)d_in[3];
    const float* c2w = (const float*)d_in[4];
    const float* c2b = (const float*)d_in[5];
    const float* enc_wq = (const float*)d_in[6];
    const float* enc_wk = (const float*)d_in[7];
    const float* enc_wv = (const float*)d_in[8];
    const float* enc_rel = (const float*)d_in[9];
    const float* e_w1 = (const float*)d_in[10];
    const float* e_b1 = (const float*)d_in[11];
    const float* e_w2 = (const float*)d_in[12];
    const float* e_b2 = (const float*)d_in[13];
    const float* m_wq = (const float*)d_in[14];
    const float* m_wk = (const float*)d_in[15];
    const float* m_wv = (const float*)d_in[16];
    const float* m_rel = (const float*)d_in[17];
    const float* l1w = (const float*)d_in[18];
    const float* l1b = (const float*)d_in[19];
    const float* l2w = (const float*)d_in[20];
    const float* l2b = (const float*)d_in[21];
    const float* c_wq = (const float*)d_in[22];
    const float* c_wk = (const float*)d_in[23];
    const float* c_wv = (const float*)d_in[24];
    const float* c_rel = (const float*)d_in[25];
    const float* d_w1 = (const float*)d_in[26];
    const float* d_b1 = (const float*)d_in[27];
    const float* d_w2 = (const float*)d_in[28];
    const float* d_b2 = (const float*)d_in[29];
    const float* ow = (const float*)d_in[30];
    const float* ob = (const float*)d_in[31];

    float *c1, *xe, *xd, *q, *k, *z, *cm, *cs, *ao, *t1, *t2, *t3, *yv;
    __half *ha, *hb, *xeh, *xdh, *t1h, *t2h, *t3h;
    cudaGetSymbolAddress((void**)&c1, g_c1);
    cudaGetSymbolAddress((void**)&xe, g_xe);
    cudaGetSymbolAddress((void**)&xd, g_xd);
    cudaGetSymbolAddress((void**)&q,  g_q);
    cudaGetSymbolAddress((void**)&k,  g_k);
    cudaGetSymbolAddress((void**)&z,  g_z);
    cudaGetSymbolAddress((void**)&cm, g_cmax);
    cudaGetSymbolAddress((void**)&cs, g_csum);
    cudaGetSymbolAddress((void**)&ao, g_ao);
    cudaGetSymbolAddress((void**)&t1, g_t1);
    cudaGetSymbolAddress((void**)&t2, g_t2);
    cudaGetSymbolAddress((void**)&t3, g_t3);
    cudaGetSymbolAddress((void**)&yv, g_y);
    cudaGetSymbolAddress((void**)&ha, g_a);
    cudaGetSymbolAddress((void**)&hb, g_b);
    cudaGetSymbolAddress((void**)&xeh, g_xeh);
    cudaGetSymbolAddress((void**)&xdh, g_xdh);
    cudaGetSymbolAddress((void**)&t1h, g_t1h);
    cudaGetSymbolAddress((void**)&t2h, g_t2h);
    cudaGetSymbolAddress((void**)&t3h, g_t3h);

    cudaFuncSetAttribute(mma_gemm_k, cudaFuncAttributeMaxDynamicSharedMemorySize, 81920);

    const int M = 43200;
    const unsigned smem_bytes = 81920;
    dim3 agrid(900, 8);
    dim3 g256(2, 338);
    dim3 g512(4, 338);
    dim3 g768(6, 338);
    dim3 g1024(8, 338);
    const float* nobias = 0;
    __half* noh = 0;

    // ---- conv stacks ----
    w_h_k<<<320, 256>>>(c1w, hb, 256, 288, 320);
    im2col1_h<<<54000, 256>>>(X_en, ha);
    mma_gemm_k<<<g256, 256, smem_bytes>>>(ha, hb, c1b, c1, noh, M, 256, 320, 2);
    w_h_k<<<2304, 256>>>(c2w, hb, 256, 2304, 2304);
    im2col2_h<<<388800, 256>>>(c1, ha);
    mma_gemm_k<<<g256, 256, smem_bytes>>>(ha, hb, c2b, xe, xeh, M, 256, 2304, 5);

    w_h_k<<<320, 256>>>(c1w, hb, 256, 288, 320);
    im2col1_h<<<54000, 256>>>(X_de, ha);
    mma_gemm_k<<<g256, 256, smem_bytes>>>(ha, hb, c1b, c1, noh, M, 256, 320, 2);
    w_h_k<<<2304, 256>>>(c2w, hb, 256, 2304, 2304);
    im2col2_h<<<388800, 256>>>(c1, ha);
    mma_gemm_k<<<g256, 256, smem_bytes>>>(ha, hb, c2b, xd, xdh, M, 256, 2304, 5);

    // ---- encoder ----
    w_h_k<<<256, 256>>>(enc_wq, hb, 256, 256, 256);
    w_h_k<<<256, 256>>>(enc_wk, hb + 65536, 256, 256, 256);
    w_h_k<<<256, 256>>>(enc_wv, hb + 131072, 256, 256, 256);
    mma_gemm_k<<<g768, 256, smem_bytes>>>(xeh, hb, nobias, q, noh, M, 768, 256, 0);
    attn_scores_k<<<agrid, 256>>>(q, q + 256, enc_rel, z, 768, 768);
    col_max_k<<<72, 256>>>(z, cm);
    col_expsum_k<<<72, 256>>>(z, cm, cs);
    attn_out_k<<<agrid, 256>>>(z, cs, q + 512, ao, 768);
    add_ln_k<<<43200, 256>>>(xe, ao, t1, t1h);
    w_h_k<<<1024, 256>>>(e_w1, hb, 1024, 256, 256);
    mma_gemm_k<<<g1024, 256, smem_bytes>>>(t1h, hb, e_b1, xe, ha, M, 1024, 256, 3);
    w_h_k<<<1024, 256>>>(e_w2, hb, 256, 1024, 1024);
    mma_gemm_k<<<g256, 256, smem_bytes>>>(ha, hb, e_b2, ao, noh, M, 256, 1024, 0);
    add_ln_k<<<43200, 256>>>(t1, ao, t2, t2h);

    // ---- decoder masked self-attn ----
    w_h_k<<<256, 256>>>(m_wq, hb, 256, 256, 256);
    w_h_k<<<256, 256>>>(m_wk, hb + 65536, 256, 256, 256);
    w_h_k<<<256, 256>>>(m_wv, hb + 131072, 256, 256, 256);
    mma_gemm_k<<<g768, 256, smem_bytes>>>(xdh, hb, nobias, q, noh, M, 768, 256, 0);
    attn_scores_masked_k<<<agrid, 256>>>(q, q + 256, m_rel, l1w, l1b, l2w, l2b, z, 768, 768);
    col_max_k<<<72, 256>>>(z, cm);
    col_expsum_k<<<72, 256>>>(z, cm, cs);
    attn_out_k<<<agrid, 256>>>(z, cs, q + 512, ao, 768);
    add_ln_k<<<43200, 256>>>(xd, ao, t1, t1h);

    // ---- decoder cross-attn ----
    w_h_k<<<256, 256>>>(c_wq, hb, 256, 256, 256);
    mma_gemm_k<<<g256, 256, smem_bytes>>>(t1h, hb, nobias, q, noh, M, 256, 256, 0);
    w_h_k<<<256, 256>>>(c_wk, hb, 256, 256, 256);
    w_h_k<<<256, 256>>>(c_wv, hb + 65536, 256, 256, 256);
    mma_gemm_k<<<g512, 256, smem_bytes>>>(t2h, hb, nobias, k, noh, M, 512, 256, 0);
    attn_scores_k<<<agrid, 256>>>(q, k, c_rel, z, 256, 512);
    col_max_k<<<72, 256>>>(z, cm);
    col_expsum_k<<<72, 256>>>(z, cm, cs);
    attn_out_k<<<agrid, 256>>>(z, cs, k + 256, ao, 512);
    add_ln_k<<<43200, 256>>>(ao, t1, t3, t3h);
    w_h_k<<<1024, 256>>>(d_w1, hb, 1024, 256, 256);
    mma_gemm_k<<<g1024, 256, smem_bytes>>>(t3h, hb, d_b1, xe, ha, M, 1024, 256, 3);
    w_h_k<<<1024, 256>>>(d_w2, hb, 256, 1024, 1024);
    mma_gemm_k<<<g256, 256, smem_bytes>>>(ha, hb, d_b2, ao, noh, M, 256, 1024, 0);
    add_ln_k<<<43200, 256>>>(t3, ao, t1, noh);

    outproj_k<<<5400, 256>>>(t1, ow, ob, yv);
    final_softmax_k<<<4, 256>>>(yv, (float*)d_out);
}

__device__ __forceinline__ unsigned smem_u32(const void* p)
{
    unsigned a;
    asm("{ .reg .u64 t; cvta.to.shared.u64 t, %1; cvt.u32.u64 %0, t; }" : "=r"(a) : "l"(p));
    return a;
}

__device__ __forceinline__ void mma16816(float* c, const unsigned* a, unsigned b0, unsigned b1)
{
    asm volatile("mma.sync.aligned.m16n8k16.row.col.f32.f16.f16.f32 {%0,%1,%2,%3}, {%4,%5,%6,%7}, {%8,%9}, {%0,%1,%2,%3};" : "+f"(c[0]), "+f"(c[1]), "+f"(c[2]), "+f"(c[3]) : "r"(a[0]), "r"(a[1]), "r"(a[2]), "r"(a[3]), "r"(b0), "r"(b1));
}

__device__ __forceinline__ void ldmx4(unsigned* r, unsigned addr)
{
    asm volatile("ldmatrix.sync.aligned.m8n8.x4.shared.b16 {%0,%1,%2,%3}, [%4];" : "=r"(r[0]), "=r"(r[1]), "=r"(r[2]), "=r"(r[3]) : "r"(addr));
}

__device__ __forceinline__ void stage_issue(
    const __half* A, const __half* B,
    unsigned st, int m0, int n0, int M, int K, int koff, int tid)
{
    for (int j = 0; j < 4; j++) {
        int i = tid + j * 256;
        int t = i >> 9;
        int r = (i >> 2) & 127;
        int c = i & 3;
        const __half* bp;
        int row;
        if (t == 0) {
            row = m0 + r;
            if (row >= M) row = M - 1;
            bp = A;
        } else {
            row = n0 + r;
            bp = B;
        }
        const __half* g = bp + (size_t)row * K + koff + c * 8;
        unsigned s = st + t * 10240 + r * 80 + c * 16;
        asm volatile("cp.async.ca.shared.global [%0], [%1], 16;" :: "r"(s), "l"(g) : "memory");
    }
    asm volatile("cp.async.commit_group;" ::: "memory");
}

__global__ __launch_bounds__(256, 2) void mma_gemm_k(
    const __half* A, const __half* B,
    const float* bias, float* C, __half* H,
    int M, int N, int K, int mode)
{
    extern __shared__ char smem[];
    const int tid = threadIdx.x;
    const int m0 = blockIdx.y * 128;
    const int n0 = blockIdx.x * 128;
    const int warp = tid >> 5;
    const int lane = tid & 31;
    const int wm = warp & 3;
    const int wn = warp >> 2;
    const int gid = lane >> 2;
    const int tig = lane & 3;
    const unsigned sbase = smem_u32(smem);

    const int arow = wm * 32 + (lane & 15);
    const int acolb = ((lane >> 4) & 1) * 16;
    const int nrow = (lane & 7) + ((lane >> 4) & 1) * 8;
    const int bcolb = ((lane >> 3) & 1) * 16;

    float acc[2][8][4];
    for (int mf = 0; mf < 2; mf++)
        for (int nf = 0; nf < 8; nf++)
            for (int e = 0; e < 4; e++)
                acc[mf][nf][e] = 0.f;

    const int nk = K >> 5;
    int pre = nk < 3 ? nk : 3;
    for (int i = 0; i < pre; i++) {
        stage_issue(A, B, sbase + (unsigned)(i & 3) * 20480u, m0, n0, M, K, i * 32, tid);
    }

    for (int kb = 0; kb < nk; kb++) {
        int pending = nk - kb;
        if (pending > 3) pending = 3;
        if (pending == 3) {
            asm volatile("cp.async.wait_group 2;" ::: "memory");
        } else if (pending == 2) {
            asm volatile("cp.async.wait_group 1;" ::: "memory");
        } else {
            asm volatile("cp.async.wait_group 0;" ::: "memory");
        }
        __syncthreads();

        const unsigned st = sbase + (unsigned)(kb & 3) * 20480u;
        for (int ks = 0; ks < 2; ks++) {
            const int kbyte = ks * 32;
            unsigned af[2][4];
            for (int mf = 0; mf < 2; mf++) {
                const unsigned arowoff = (unsigned)(arow + mf * 16) * 80u + kbyte + acolb;
                ldmx4(af[mf], st + arowoff);
            }
            for (int nfg = 0; nfg < 4; nfg++) {
                const unsigned browoff = (unsigned)(wn * 64 + nfg * 16 + nrow) * 80u + kbyte + bcolb;
                unsigned b4[4];
                ldmx4(b4, st + 10240u + browoff);
                for (int sub = 0; sub < 2; sub++) {
                    const int nf = nfg * 2 + sub;
                    for (int mf = 0; mf < 2; mf++) {
                        mma16816(acc[mf][nf], af[mf], b4[sub * 2], b4[sub * 2 + 1]);
                    }
                }
            }
        }
        if (kb + 3 < nk) {
            stage_issue(A, B, sbase + (unsigned)((kb + 3) & 3) * 20480u, m0, n0, M, K, (kb + 3) * 32, tid);
        }
    }

    for (int mf = 0; mf < 2; mf++) {
        for (int nf = 0; nf < 8; nf++) {
            const int col = n0 + wn * 64 + nf * 8 + tig * 2;
            float bv0 = 0.f;
            float bv1 = 0.f;
            if (bias) {
                bv0 = bias[col];
                bv1 = bias[col + 1];
            }
            for (int half2i = 0; half2i < 2; half2i++) {
                const int m = m0 + wm * 32 + mf * 16 + gid + half2i * 8;
                if (m < M) {
                    float v0 = acc[mf][nf][half2i * 2 + 0] + bv0;
                    float v1 = acc[mf][nf][half2i * 2 + 1] + bv1;
                    if (mode == 3) {
                        v0 = fmaxf(v0, 0.f);
                        v1 = fmaxf(v1, 0.f);
                        __half* hrow = H + (size_t)m * N + col;
                        hrow[0] = __float2half(v0);
                        hrow[1] = __float2half(v1);
                    } else if (mode == 2 || mode == 5) {
                        const int b = m / 900;
                        const int p = m - b * 900;
                        size_t off = (size_t)b * 230400 + (size_t)col * 900 + p;
                        C[off] = v0;
                        C[off + 900] = v1;
                        if (mode == 5) {
                            H[off] = __float2half(v0);
                            H[off + 900] = __float2half(v1);
                        }
                    } else {
                        float2 stv;
                        stv.x = v0;
                        stv.y = v1;
                        *(float2*)(C + (size_t)m * N + col) = stv;
                    }
                }
            }
        }
    }
}

__global__ __launch_bounds__(256) void w_h_k(const float* w, __half* out, int N, int K, int Kp)
{
    int i = blockIdx.x * 256 + threadIdx.x;
    if (i >= N * Kp) return;
    int r = i / Kp;
    int k = i - r * Kp;
    float v = 0.f;
    if (k < K) v = w[(size_t)r * K + k];
    out[i] = __float2half(v);
}

__global__ __launch_bounds__(256) void im2col1_h(const float* X, __half* out)
{
    unsigned i = blockIdx.x * 256u + threadIdx.x;
    if (i >= 13824000u) return;
    int m = (int)(i / 320u);
    int k = (int)(i - (unsigned)m * 320u);
    float v = 0.f;
    if (k < 288) {
        int ic = k / 9;
        int r9 = k - ic * 9;
        int ky = r9 / 3;
        int kx = r9 - ky * 3;
        int b = m / 900;
        int p = m - b * 900;
        int y = p / 30;
        int x = p - y * 30;
        v = X[((size_t)(b * 32 + ic) * 32 + (y + ky)) * 32 + (x + kx)];
    }
    out[i] = __float2half(v);
}

__global__ __launch_bounds__(256) void im2col2_h(const float* in, __half* out)
{
    unsigned i = blockIdx.x * 256u + threadIdx.x;
    if (i >= 99532800u) return;
    int m = (int)(i / 2304u);
    int k = (int)(i - (unsigned)m * 2304u);
    int ic = k / 9;
    int r9 = k - ic * 9;
    int ky = r9 / 3;
    int kx = r9 - ky * 3;
    int b = m / 900;
    int p = m - b * 900;
    int y = p / 30;
    int x = p - y * 30;
    int iy = y + ky - 1;
    int ix = x + kx - 1;
    float v = 0.f;
    if (iy >= 0 && iy < 30 && ix >= 0 && ix < 30) {
        v = in[(size_t)(b * 256 + ic) * 900 + iy * 30 + ix];
    }
    out[i] = __float2half(v);
}

__global__ __launch_bounds__(256) void attn_scores_k(
    const float* Q, const float* Kb, const float* RW, float* Z, int qs, int ks)
{
    const int s = blockIdx.x;
    const int h = blockIdx.y;
    const int tid = threadIdx.x;
    __shared__ float sq[48][33];
    __shared__ float sk[48][33];
    __shared__ float sw[32][49];
    __shared__ float se[48][49];
    for (int e = tid; e < 1536; e += 256) {
        int i = e >> 5;
        int d = e & 31;
        sq[i][d] = Q [(size_t)(s * 48 + i) * qs + h * 32 + d];
        sk[i][d] = Kb[(size_t)(s * 48 + i) * ks + h * 32 + d];
    }
    for (int e = tid; e < 1536; e += 256) {
        int d = e / 48;
        int j = e - d * 48;
        sw[d][j] = RW[(((size_t)s * 8 + h) * 32 + d) * 48 + j];
    }
    __syncthreads();
    float scv[9];
    for (int it = 0; it < 9; it++) {
        int e = tid + it * 256;
        int i = e / 48;
        int j = e - i * 48;
        float sc = 0.f;
        float em = 0.f;
        for (int d = 0; d < 32; d++) {
            float qv = sq[i][d];
            sc += qv * sk[j][d];
            em += qv * sw[d][j];
        }
        scv[it] = sc * 0.17677669529663689f;
        se[i][j] = em;
    }
    __syncthreads();
    size_t base = (size_t)s * 18432 + (size_t)h * 2304;
    for (int it = 0; it < 9; it++) {
        int e = tid + it * 256;
        int i = e / 48;
        int j = e - i * 48;
        float zz = scv[it];
        if (j <= i) zz += se[i][47 - i + j];
        Z[base + e] = zz;
    }
}

__global__ __launch_bounds__(256) void attn_scores_masked_k(
    const float* Q, const float* Kb, const float* RW,
    const float* L1w, const float* L1b,
    const float* L2w, const float* L2b, float* Z, int qs, int ks)
{
    const int s = blockIdx.x;
    const int h = blockIdx.y;
    const int tid = threadIdx.x;
    __shared__ float sq[48][33];
    __shared__ float sk[48][33];
    __shared__ float sw[32][49];
    __shared__ float se[48][49];
    __shared__ float ss[48][49];
    __shared__ float s1[48][49];
    for (int e = tid; e < 1536; e += 256) {
        int i = e >> 5;
        int d = e & 31;
        sq[i][d] = Q [(size_t)(s * 48 + i) * qs + h * 32 + d];
        sk[i][d] = Kb[(size_t)(s * 48 + i) * ks + h * 32 + d];
    }
    for (int e = tid; e < 1536; e += 256) {
        int d = e / 48;
        int j = e - d * 48;
        sw[d][j] = RW[(((size_t)s * 8 + h) * 32 + d) * 48 + j];
    }
    __syncthreads();
    for (int e = tid; e < 2304; e += 256) {
        int i = e / 48;
        int j = e - i * 48;
        float sc = 0.f;
        float em = 0.f;
        for (int d = 0; d < 32; d++) {
            float qv = sq[i][d];
            sc += qv * sk[j][d];
            em += qv * sw[d][j];
        }
        ss[i][j] = sc * 0.17677669529663689f;
        se[i][j] = em;
    }
    __syncthreads();
    for (int e = tid; e < 2304; e += 256) {
        int i = e / 48;
        int j = e - i * 48;
        float acc = L1b[j];
        for (int c = 0; c < 48; c++) acc += ss[i][c] * __ldg(&L1w[j * 48 + c]);
        s1[i][j] = acc;
    }
    __syncthreads();
    size_t base = (size_t)s * 18432 + (size_t)h * 2304;
    for (int e = tid; e < 2304; e += 256) {
        int a = e / 48;
        int b = e - a * 48;
        float acc = L2b[b];
        for (int c = 0; c < 48; c++) acc += s1[c][a] * __ldg(&L2w[b * 48 + c]);
        if (b > a) acc -= 3.402823466e+38f;
        if (b <= a) acc += se[a][47 - a + b];
        Z[base + e] = acc;
    }
}

__global__ __launch_bounds__(256) void col_max_k(const float* Z, float* cmax)
{
    int c = blockIdx.x * 256 + threadIdx.x;
    const float* p = Z + c;
    float m = -3.402823466e+38f;
    for (int s = 0; s < 900; s++) m = fmaxf(m, p[(size_t)s * 18432]);
    cmax[c] = m;
}

__global__ __launch_bounds__(256) void col_expsum_k(float* Z, const float* cmax, float* csum)
{
    int c = blockIdx.x * 256 + threadIdx.x;
    float m = cmax[c];
    float* p = Z + c;
    float sum = 0.f;
    for (int s = 0; s < 900; s++) {
        float v = __expf(p[(size_t)s * 18432] - m);
        p[(size_t)s * 18432] = v;
        sum += v;
    }
    csum[c] = sum;
}

__global__ __launch_bounds__(256) void attn_out_k(
    const float* Z, const float* csum, const float* V, float* O, int vs)
{
    const int s = blockIdx.x;
    const int h = blockIdx.y;
    const int tid = threadIdx.x;
    __shared__ float sp[48][49];
    __shared__ float sv[48][33];
    size_t base = (size_t)s * 18432 + (size_t)h * 2304;
    for (int e = tid; e < 2304; e += 256) {
        int i = e / 48;
        int j = e - i * 48;
        sp[i][j] = Z[base + e] / csum[h * 2304 + e];
    }
    for (int e = tid; e < 1536; e += 256) {
        int j = e >> 5;
        int d = e & 31;
        sv[j][d] = V[(size_t)(s * 48 + j) * vs + h * 32 + d];
    }
    __syncthreads();
    for (int e = tid; e < 1536; e += 256) {
        int i = e >> 5;
        int d = e & 31;
        float acc = 0.f;
        for (int j = 0; j < 48; j++) acc += sp[i][j] * sv[j][d];
        O[(size_t)((s * 8 + h) * 48 + i) * 32 + d] = acc;
    }
}

__device__ __forceinline__ float block_sum256(float v, float* sbuf)
{
    for (int o = 16; o > 0; o >>= 1) v += __shfl_down_sync(0xffffffffu, v, o);
    int w = threadIdx.x >> 5;
    int l = threadIdx.x & 31;
    if (l == 0) sbuf[w] = v;
    __syncthreads();
    if (w == 0) {
        v = (l < 8) ? sbuf[l] : 0.f;
        for (int o = 4; o > 0; o >>= 1) v += __shfl_down_sync(0xffffffffu, v, o);
        if (l == 0) sbuf[0] = v;
    }
    __syncthreads();
    float r = sbuf[0];
    __syncthreads();
    return r;
}

__global__ __launch_bounds__(256) void add_ln_k(const float* A, const float* B, float* O, __half* H)
{
    __shared__ float sbuf[8];
    size_t base = (size_t)blockIdx.x * 256;
    float v = A[base + threadIdx.x] + B[base + threadIdx.x];
    float mean = block_sum256(v, sbuf) * (1.f / 256.f);
    float d = v - mean;
    float var = block_sum256(d * d, sbuf) * (1.f / 256.f);
    float r = d * rsqrtf(var + 1e-5f);
    O[base + threadIdx.x] = r;
    if (H) H[base + threadIdx.x] = __float2half(r);
}

__global__ __launch_bounds__(256) void outproj_k(const float* H, const float* w,
                                                 const float* b, float* y)
{
    int warp = (blockIdx.x * 256 + threadIdx.x) >> 5;
    int lane = threadIdx.x & 31;
    if (warp >= 43200) return;
    const float* row = H + (size_t)warp * 256;
    float s = 0.f;
    for (int k = lane; k < 256; k += 32) s += row[k] * w[k];
    for (int o = 16; o > 0; o >>= 1) s += __shfl_down_sync(0xffffffffu, s, o);
    if (lane == 0) y[warp] = s + b[0];
}

__global__ __launch_bounds__(256) void final_softmax_k(const float* y, float* out)
{
    int s = blockIdx.x * 256 + threadIdx.x;
    if (s >= 900) return;
    float m = -3.402823466e+38f;
    for (int b = 0; b < 48; b++) m = fmaxf(m, y[b * 900 + s]);
    float sum = 0.f;
    for (int b = 0; b < 48; b++) sum += __expf(y[b * 900 + s] - m);
    float inv = 1.f / sum;
    for (int b = 0; b < 48; b++) out[b * 900 + s] = __expf(y[b * 900 + s] - m) * inv;
}

// round 16
// speedup vs baseline: 2.4132x; 1.8285x over previous
#include <cuda_runtime.h>
#include <cuda_fp16.h>
#include <cstdint>
#include <math.h>

__device__ float g_c1[48*256*900];
__device__ float g_xe[48*256*900];
__device__ float g_xd[48*256*900];
__device__ float g_q [48*900*768];
__device__ float g_k [48*900*512];
__device__ float g_z [900*8*48*48];
__device__ float g_cmax[8*48*48];
__device__ float g_csum[8*48*48];
__device__ float g_ao[48*900*256];
__device__ float g_t1[48*900*256];
__device__ float g_t2[48*900*256];
__device__ float g_t3[48*900*256];
__device__ float g_y [48*900];
__device__ __half g_a[99532800u];
__device__ __half g_b[2359296u];
__device__ __half g_xeh[11059200u];
__device__ __half g_xdh[11059200u];
__device__ __half g_t1h[11059200u];
__device__ __half g_t2h[11059200u];
__device__ __half g_t3h[11059200u];

__global__ void mma_gemm_k(const __half* A, const __half* B,
                           const float* bias, float* C, __half* H,
                           int M, int N, int K, int mode);
__global__ void w_h_k(const float* w, __half* out, int N, int K, int Kp);
__global__ void im2col1_h(const float* X, __half* out);
__global__ void im2col2_h(const float* in, __half* out);
__global__ void attn_scores_k(const float* Q, const float* Kb, const float* RW, float* Z,
                              int qs, int ks);
__global__ void attn_scores_masked_k(const float* Q, const float* Kb, const float* RW,
                                     const float* L1w, const float* L1b,
                                     const float* L2w, const float* L2b, float* Z,
                                     int qs, int ks);
__global__ void col_max_k(const float* Z, float* cmax);
__global__ void col_expsum_k(float* Z, const float* cmax, float* csum);
__global__ void attn_out_k(const float* Z, const float* csum, const float* V, float* O, int vs);
__global__ void add_ln_k(const float* A, const float* B, float* O, __half* H);
__global__ void outproj_k(const float* H, const float* w, const float* b, float* y);
__global__ void final_softmax_k(const float* y, float* out);

extern "C" void kernel_launch(void* const* d_in, const int* in_sizes, int n_in,
                              void* d_out, int out_size)
{
    const float* X_en = (const float*)d_in[0];
    const float* X_de = (const float*)d_in[1];
    const float* c1w = (const float*)d_in[2];
    const float* c1b = (const float*)d_in[3];
    const float* c2w = (const float*)d_in[4];
    const float* c2b = (const float*)d_in[5];
    const float* enc_wq = (const float*)d_in[6];
    const float* enc_wk = (const float*)d_in[7];
    const float* enc_wv = (const float*)d_in[8];
    const float* enc_rel = (const float*)d_in[9];
    const float* e_w1 = (const float*)d_in[10];
    const float* e_b1 = (const float*)d_in[11];
    const float* e_w2 = (const float*)d_in[12];
    const float* e_b2 = (const float*)d_in[13];
    const float* m_wq = (const float*)d_in[14];
    const float* m_wk = (const float*)d_in[15];
    const float* m_wv = (const float*)d_in[16];
    const float* m_rel = (const float*)d_in[17];
    const float* l1w = (const float*)d_in[18];
    const float* l1b = (const float*)d_in[19];
    const float* l2w = (const float*)d_in[20];
    const float* l2b = (const float*)d_in[21];
    const float* c_wq = (const float*)d_in[22];
    const float* c_wk = (const float*)d_in[23];
    const float* c_wv = (const float*)d_in[24];
    const float* c_rel = (const float*)d_in[25];
    const float* d_w1 = (const float*)d_in[26];
    const float* d_b1 = (const float*)d_in[27];
    const float* d_w2 = (const float*)d_in[28];
    const float* d_b2 = (const float*)d_in[29];
    const float* ow = (const float*)d_in[30];
    const float* ob = (const float*)d_in[31];

    float *c1, *xe, *xd, *q, *k, *z, *cm, *cs, *ao, *t1, *t2, *t3, *yv;
    __half *ha, *hb, *xeh, *xdh, *t1h, *t2h, *t3h;
    cudaGetSymbolAddress((void**)&c1, g_c1);
    cudaGetSymbolAddress((void**)&xe, g_xe);
    cudaGetSymbolAddress((void**)&xd, g_xd);
    cudaGetSymbolAddress((void**)&q,  g_q);
    cudaGetSymbolAddress((void**)&k,  g_k);
    cudaGetSymbolAddress((void**)&z,  g_z);
    cudaGetSymbolAddress((void**)&cm, g_cmax);
    cudaGetSymbolAddress((void**)&cs, g_csum);
    cudaGetSymbolAddress((void**)&ao, g_ao);
    cudaGetSymbolAddress((void**)&t1, g_t1);
    cudaGetSymbolAddress((void**)&t2, g_t2);
    cudaGetSymbolAddress((void**)&t3, g_t3);
    cudaGetSymbolAddress((void**)&yv, g_y);
    cudaGetSymbolAddress((void**)&ha, g_a);
    cudaGetSymbolAddress((void**)&hb, g_b);
    cudaGetSymbolAddress((void**)&xeh, g_xeh);
    cudaGetSymbolAddress((void**)&xdh, g_xdh);
    cudaGetSymbolAddress((void**)&t1h, g_t1h);
    cudaGetSymbolAddress((void**)&t2h, g_t2h);
    cudaGetSymbolAddress((void**)&t3h, g_t3h);

    cudaFuncSetAttribute(mma_gemm_k, cudaFuncAttributeMaxDynamicSharedMemorySize, 81920);

    const int M = 43200;
    const unsigned smem_bytes = 81920;
    dim3 agrid(900, 8);
    dim3 g256(2, 338);
    dim3 g512(4, 338);
    dim3 g768(6, 338);
    dim3 g1024(8, 338);
    const float* nobias = 0;
    __half* noh = 0;

    // ---- conv stacks ----
    w_h_k<<<320, 256>>>(c1w, hb, 256, 288, 320);
    im2col1_h<<<54000, 256>>>(X_en, ha);
    mma_gemm_k<<<g256, 256, smem_bytes>>>(ha, hb, c1b, c1, noh, M, 256, 320, 2);
    w_h_k<<<2304, 256>>>(c2w, hb, 256, 2304, 2304);
    im2col2_h<<<388800, 256>>>(c1, ha);
    mma_gemm_k<<<g256, 256, smem_bytes>>>(ha, hb, c2b, xe, xeh, M, 256, 2304, 5);

    w_h_k<<<320, 256>>>(c1w, hb, 256, 288, 320);
    im2col1_h<<<54000, 256>>>(X_de, ha);
    mma_gemm_k<<<g256, 256, smem_bytes>>>(ha, hb, c1b, c1, noh, M, 256, 320, 2);
    w_h_k<<<2304, 256>>>(c2w, hb, 256, 2304, 2304);
    im2col2_h<<<388800, 256>>>(c1, ha);
    mma_gemm_k<<<g256, 256, smem_bytes>>>(ha, hb, c2b, xd, xdh, M, 256, 2304, 5);

    // ---- encoder ----
    w_h_k<<<256, 256>>>(enc_wq, hb, 256, 256, 256);
    w_h_k<<<256, 256>>>(enc_wk, hb + 65536, 256, 256, 256);
    w_h_k<<<256, 256>>>(enc_wv, hb + 131072, 256, 256, 256);
    mma_gemm_k<<<g768, 256, smem_bytes>>>(xeh, hb, nobias, q, noh, M, 768, 256, 0);
    attn_scores_k<<<agrid, 256>>>(q, q + 256, enc_rel, z, 768, 768);
    col_max_k<<<72, 256>>>(z, cm);
    col_expsum_k<<<72, 256>>>(z, cm, cs);
    attn_out_k<<<agrid, 256>>>(z, cs, q + 512, ao, 768);
    add_ln_k<<<43200, 256>>>(xe, ao, t1, t1h);
    w_h_k<<<1024, 256>>>(e_w1, hb, 1024, 256, 256);
    mma_gemm_k<<<g1024, 256, smem_bytes>>>(t1h, hb, e_b1, xe, ha, M, 1024, 256, 3);
    w_h_k<<<1024, 256>>>(e_w2, hb, 256, 1024, 1024);
    mma_gemm_k<<<g256, 256, smem_bytes>>>(ha, hb, e_b2, ao, noh, M, 256, 1024, 0);
    add_ln_k<<<43200, 256>>>(t1, ao, t2, t2h);

    // ---- decoder masked self-attn ----
    w_h_k<<<256, 256>>>(m_wq, hb, 256, 256, 256);
    w_h_k<<<256, 256>>>(m_wk, hb + 65536, 256, 256, 256);
    w_h_k<<<256, 256>>>(m_wv, hb + 131072, 256, 256, 256);
    mma_gemm_k<<<g768, 256, smem_bytes>>>(xdh, hb, nobias, q, noh, M, 768, 256, 0);
    attn_scores_masked_k<<<agrid, 256>>>(q, q + 256, m_rel, l1w, l1b, l2w, l2b, z, 768, 768);
    col_max_k<<<72, 256>>>(z, cm);
    col_expsum_k<<<72, 256>>>(z, cm, cs);
    attn_out_k<<<agrid, 256>>>(z, cs, q + 512, ao, 768);
    add_ln_k<<<43200, 256>>>(xd, ao, t1, t1h);

    // ---- decoder cross-attn ----
    w_h_k<<<256, 256>>>(c_wq, hb, 256, 256, 256);
    mma_gemm_k<<<g256, 256, smem_bytes>>>(t1h, hb, nobias, q, noh, M, 256, 256, 0);
    w_h_k<<<256, 256>>>(c_wk, hb, 256, 256, 256);
    w_h_k<<<256, 256>>>(c_wv, hb + 65536, 256, 256, 256);
    mma_gemm_k<<<g512, 256, smem_bytes>>>(t2h, hb, nobias, k, noh, M, 512, 256, 0);
    attn_scores_k<<<agrid, 256>>>(q, k, c_rel, z, 256, 512);
    col_max_k<<<72, 256>>>(z, cm);
    col_expsum_k<<<72, 256>>>(z, cm, cs);
    attn_out_k<<<agrid, 256>>>(z, cs, k + 256, ao, 512);
    add_ln_k<<<43200, 256>>>(ao, t1, t3, t3h);
    w_h_k<<<1024, 256>>>(d_w1, hb, 1024, 256, 256);
    mma_gemm_k<<<g1024, 256, smem_bytes>>>(t3h, hb, d_b1, xe, ha, M, 1024, 256, 3);
    w_h_k<<<1024, 256>>>(d_w2, hb, 256, 1024, 1024);
    mma_gemm_k<<<g256, 256, smem_bytes>>>(ha, hb, d_b2, ao, noh, M, 256, 1024, 0);
    add_ln_k<<<43200, 256>>>(t3, ao, t1, noh);

    outproj_k<<<5400, 256>>>(t1, ow, ob, yv);
    final_softmax_k<<<4, 256>>>(yv, (float*)d_out);
}

__device__ __forceinline__ unsigned smem_u32(const void* p)
{
    unsigned a;
    asm("{ .reg .u64 t; cvta.to.shared.u64 t, %1; cvt.u32.u64 %0, t; }" : "=r"(a) : "l"(p));
    return a;
}

__device__ __forceinline__ void mma16816(float* c, const unsigned* a, unsigned b0, unsigned b1)
{
    asm volatile("mma.sync.aligned.m16n8k16.row.col.f32.f16.f16.f32 {%0,%1,%2,%3}, {%4,%5,%6,%7}, {%8,%9}, {%0,%1,%2,%3};" : "+f"(c[0]), "+f"(c[1]), "+f"(c[2]), "+f"(c[3]) : "r"(a[0]), "r"(a[1]), "r"(a[2]), "r"(a[3]), "r"(b0), "r"(b1));
}

__device__ __forceinline__ void ldmx4(unsigned* r, unsigned addr)
{
    asm volatile("ldmatrix.sync.aligned.m8n8.x4.shared.b16 {%0,%1,%2,%3}, [%4];" : "=r"(r[0]), "=r"(r[1]), "=r"(r[2]), "=r"(r[3]) : "r"(addr));
}

__device__ __forceinline__ void stage_issue(
    const __half* A, const __half* B,
    unsigned st, int m0, int n0, int M, int K, int koff, int tid)
{
    for (int j = 0; j < 4; j++) {
        int i = tid + j * 256;
        int t = i >> 9;
        int r = (i >> 2) & 127;
        int c = i & 3;
        const __half* bp;
        int row;
        if (t == 0) {
            row = m0 + r;
            if (row >= M) row = M - 1;
            bp = A;
        } else {
            row = n0 + r;
            bp = B;
        }
        const __half* g = bp + (size_t)row * K + koff + c * 8;
        unsigned s = st + t * 10240 + r * 80 + c * 16;
        asm volatile("cp.async.ca.shared.global [%0], [%1], 16;" :: "r"(s), "l"(g) : "memory");
    }
    asm volatile("cp.async.commit_group;" ::: "memory");
}

__global__ __launch_bounds__(256, 2) void mma_gemm_k(
    const __half* A, const __half* B,
    const float* bias, float* C, __half* H,
    int M, int N, int K, int mode)
{
    extern __shared__ char smem[];
    const int tid = threadIdx.x;
    const int m0 = blockIdx.y * 128;
    const int n0 = blockIdx.x * 128;
    const int warp = tid >> 5;
    const int lane = tid & 31;
    const int wm = warp & 3;
    const int wn = warp >> 2;
    const int gid = lane >> 2;
    const int tig = lane & 3;
    const unsigned sbase = smem_u32(smem);

    const int arow = wm * 32 + (lane & 15);
    const int acolb = ((lane >> 4) & 1) * 16;
    const int nrow = (lane & 7) + ((lane >> 4) & 1) * 8;
    const int bcolb = ((lane >> 3) & 1) * 16;

    float acc[2][8][4];
    for (int mf = 0; mf < 2; mf++)
        for (int nf = 0; nf < 8; nf++)
            for (int e = 0; e < 4; e++)
                acc[mf][nf][e] = 0.f;

    const int nk = K >> 5;
    int pre = nk < 3 ? nk : 3;
    for (int i = 0; i < pre; i++) {
        stage_issue(A, B, sbase + (unsigned)(i & 3) * 20480u, m0, n0, M, K, i * 32, tid);
    }

    for (int kb = 0; kb < nk; kb++) {
        int pending = nk - kb;
        if (pending > 3) pending = 3;
        if (pending == 3) {
            asm volatile("cp.async.wait_group 2;" ::: "memory");
        } else if (pending == 2) {
            asm volatile("cp.async.wait_group 1;" ::: "memory");
        } else {
            asm volatile("cp.async.wait_group 0;" ::: "memory");
        }
        __syncthreads();

        const unsigned st = sbase + (unsigned)(kb & 3) * 20480u;
        for (int ks = 0; ks < 2; ks++) {
            const int kbyte = ks * 32;
            unsigned af[2][4];
            for (int mf = 0; mf < 2; mf++) {
                const unsigned arowoff = (unsigned)(arow + mf * 16) * 80u + kbyte + acolb;
                ldmx4(af[mf], st + arowoff);
            }
            for (int nfg = 0; nfg < 4; nfg++) {
                const unsigned browoff = (unsigned)(wn * 64 + nfg * 16 + nrow) * 80u + kbyte + bcolb;
                unsigned b4[4];
                ldmx4(b4, st + 10240u + browoff);
                for (int sub = 0; sub < 2; sub++) {
                    const int nf = nfg * 2 + sub;
                    for (int mf = 0; mf < 2; mf++) {
                        mma16816(acc[mf][nf], af[mf], b4[sub * 2], b4[sub * 2 + 1]);
                    }
                }
            }
        }
        if (kb + 3 < nk) {
            stage_issue(A, B, sbase + (unsigned)((kb + 3) & 3) * 20480u, m0, n0, M, K, (kb + 3) * 32, tid);
        }
    }

    for (int mf = 0; mf < 2; mf++) {
        for (int nf = 0; nf < 8; nf++) {
            const int col = n0 + wn * 64 + nf * 8 + tig * 2;
            float bv0 = 0.f;
            float bv1 = 0.f;
            if (bias) {
                bv0 = bias[col];
                bv1 = bias[col + 1];
            }
            for (int half2i = 0; half2i < 2; half2i++) {
                const int m = m0 + wm * 32 + mf * 16 + gid + half2i * 8;
                if (m < M) {
                    float v0 = acc[mf][nf][half2i * 2 + 0] + bv0;
                    float v1 = acc[mf][nf][half2i * 2 + 1] + bv1;
                    if (mode == 3) {
                        v0 = fmaxf(v0, 0.f);
                        v1 = fmaxf(v1, 0.f);
                        __half* hrow = H + (size_t)m * N + col;
                        hrow[0] = __float2half(v0);
                        hrow[1] = __float2half(v1);
                    } else if (mode == 2 || mode == 5) {
                        const int b = m / 900;
                        const int p = m - b * 900;
                        size_t off = (size_t)b * 230400 + (size_t)col * 900 + p;
                        C[off] = v0;
                        C[off + 900] = v1;
                        if (mode == 5) {
                            H[off] = __float2half(v0);
                            H[off + 900] = __float2half(v1);
                        }
                    } else {
                        float2 stv;
                        stv.x = v0;
                        stv.y = v1;
                        *(float2*)(C + (size_t)m * N + col) = stv;
                    }
                }
            }
        }
    }
}

__global__ __launch_bounds__(256) void w_h_k(const float* w, __half* out, int N, int K, int Kp)
{
    int i = blockIdx.x * 256 + threadIdx.x;
    if (i >= N * Kp) return;
    int r = i / Kp;
    int k = i - r * Kp;
    float v = 0.f;
    if (k < K) v = w[(size_t)r * K + k];
    out[i] = __float2half(v);
}

__global__ __launch_bounds__(256) void im2col1_h(const float* X, __half* out)
{
    unsigned i = blockIdx.x * 256u + threadIdx.x;
    if (i >= 13824000u) return;
    int m = (int)(i / 320u);
    int k = (int)(i - (unsigned)m * 320u);
    float v = 0.f;
    if (k < 288) {
        int ic = k / 9;
        int r9 = k - ic * 9;
        int ky = r9 / 3;
        int kx = r9 - ky * 3;
        int b = m / 900;
        int p = m - b * 900;
        int y = p / 30;
        int x = p - y * 30;
        v = X[((size_t)(b * 32 + ic) * 32 + (y + ky)) * 32 + (x + kx)];
    }
    out[i] = __float2half(v);
}

__global__ __launch_bounds__(256) void im2col2_h(const float* in, __half* out)
{
    unsigned i = blockIdx.x * 256u + threadIdx.x;
    if (i >= 99532800u) return;
    int m = (int)(i / 2304u);
    int k = (int)(i - (unsigned)m * 2304u);
    int ic = k / 9;
    int r9 = k - ic * 9;
    int ky = r9 / 3;
    int kx = r9 - ky * 3;
    int b = m / 900;
    int p = m - b * 900;
    int y = p / 30;
    int x = p - y * 30;
    int iy = y + ky - 1;
    int ix = x + kx - 1;
    float v = 0.f;
    if (iy >= 0 && iy < 30 && ix >= 0 && ix < 30) {
        v = in[(size_t)(b * 256 + ic) * 900 + iy * 30 + ix];
    }
    out[i] = __float2half(v);
}

__global__ __launch_bounds__(256) void attn_scores_k(
    const float* Q, const float* Kb, const float* RW, float* Z, int qs, int ks)
{
    const int s = blockIdx.x;
    const int h = blockIdx.y;
    const int tid = threadIdx.x;
    __shared__ float sq[48][33];
    __shared__ float sk[48][33];
    __shared__ float sw[32][49];
    __shared__ float se[48][49];
    for (int e = tid; e < 1536; e += 256) {
        int i = e >> 5;
        int d = e & 31;
        sq[i][d] = Q [(size_t)(s * 48 + i) * qs + h * 32 + d];
        sk[i][d] = Kb[(size_t)(s * 48 + i) * ks + h * 32 + d];
    }
    for (int e = tid; e < 1536; e += 256) {
        int d = e / 48;
        int j = e - d * 48;
        sw[d][j] = RW[(((size_t)s * 8 + h) * 32 + d) * 48 + j];
    }
    __syncthreads();
    const int i0 = (tid >> 4) * 3;
    const int j0 = (tid & 15) * 3;
    float sc[3][3];
    float em[3][3];
    for (int a = 0; a < 3; a++) {
        for (int b = 0; b < 3; b++) {
            sc[a][b] = 0.f;
            em[a][b] = 0.f;
        }
    }
    for (int d = 0; d < 32; d++) {
        float qv[3];
        float kv[3];
        float wv[3];
        for (int a = 0; a < 3; a++) {
            qv[a] = sq[i0 + a][d];
            kv[a] = sk[j0 + a][d];
            wv[a] = sw[d][j0 + a];
        }
        for (int a = 0; a < 3; a++) {
            for (int b = 0; b < 3; b++) {
                sc[a][b] += qv[a] * kv[b];
                em[a][b] += qv[a] * wv[b];
            }
        }
    }
    for (int a = 0; a < 3; a++)
        for (int b = 0; b < 3; b++)
            se[i0 + a][j0 + b] = em[a][b];
    __syncthreads();
    size_t base = (size_t)s * 18432 + (size_t)h * 2304;
    for (int a = 0; a < 3; a++) {
        for (int b = 0; b < 3; b++) {
            int i = i0 + a;
            int j = j0 + b;
            float zz = sc[a][b] * 0.17677669529663689f;
            if (j <= i) zz += se[i][47 - i + j];
            Z[base + i * 48 + j] = zz;
        }
    }
}

__global__ __launch_bounds__(256) void attn_scores_masked_k(
    const float* Q, const float* Kb, const float* RW,
    const float* L1w, const float* L1b,
    const float* L2w, const float* L2b, float* Z, int qs, int ks)
{
    const int s = blockIdx.x;
    const int h = blockIdx.y;
    const int tid = threadIdx.x;
    __shared__ float sq[48][33];
    __shared__ float sk[48][33];
    __shared__ float sw[32][49];
    __shared__ float se[48][49];
    __shared__ float ss[48][49];
    __shared__ float s1[48][49];
    for (int e = tid; e < 1536; e += 256) {
        int i = e >> 5;
        int d = e & 31;
        sq[i][d] = Q [(size_t)(s * 48 + i) * qs + h * 32 + d];
        sk[i][d] = Kb[(size_t)(s * 48 + i) * ks + h * 32 + d];
    }
    for (int e = tid; e < 1536; e += 256) {
        int d = e / 48;
        int j = e - d * 48;
        sw[d][j] = RW[(((size_t)s * 8 + h) * 32 + d) * 48 + j];
    }
    __syncthreads();
    const int i0 = (tid >> 4) * 3;
    const int j0 = (tid & 15) * 3;
    float sc[3][3];
    float em[3][3];
    for (int a = 0; a < 3; a++) {
        for (int b = 0; b < 3; b++) {
            sc[a][b] = 0.f;
            em[a][b] = 0.f;
        }
    }
    for (int d = 0; d < 32; d++) {
        float qv[3];
        float kv[3];
        float wv[3];
        for (int a = 0; a < 3; a++) {
            qv[a] = sq[i0 + a][d];
            kv[a] = sk[j0 + a][d];
            wv[a] = sw[d][j0 + a];
        }
        for (int a = 0; a < 3; a++) {
            for (int b = 0; b < 3; b++) {
                sc[a][b] += qv[a] * kv[b];
                em[a][b] += qv[a] * wv[b];
            }
        }
    }
    for (int a = 0; a < 3; a++) {
        for (int b = 0; b < 3; b++) {
            ss[i0 + a][j0 + b] = sc[a][b] * 0.17677669529663689f;
            se[i0 + a][j0 + b] = em[a][b];
        }
    }
    __syncthreads();
    float p2[3][3];
    for (int b = 0; b < 3; b++) {
        float bv = L1b[j0 + b];
        for (int a = 0; a < 3; a++) p2[a][b] = bv;
    }
    for (int c = 0; c < 48; c++) {
        float sv[3];
        float wl[3];
        for (int a = 0; a < 3; a++) sv[a] = ss[i0 + a][c];
        for (int b = 0; b < 3; b++) wl[b] = __ldg(&L1w[(j0 + b) * 48 + c]);
        for (int a = 0; a < 3; a++)
            for (int b = 0; b < 3; b++)
                p2[a][b] += sv[a] * wl[b];
    }
    for (int a = 0; a < 3; a++)
        for (int b = 0; b < 3; b++)
            s1[i0 + a][j0 + b] = p2[a][b];
    __syncthreads();
    float p3[3][3];
    for (int b = 0; b < 3; b++) {
        float bv = L2b[j0 + b];
        for (int a = 0; a < 3; a++) p3[a][b] = bv;
    }
    for (int c = 0; c < 48; c++) {
        float sv[3];
        float wl[3];
        for (int a = 0; a < 3; a++) sv[a] = s1[c][i0 + a];
        for (int b = 0; b < 3; b++) wl[b] = __ldg(&L2w[(j0 + b) * 48 + c]);
        for (int a = 0; a < 3; a++)
            for (int b = 0; b < 3; b++)
                p3[a][b] += sv[a] * wl[b];
    }
    size_t base = (size_t)s * 18432 + (size_t)h * 2304;
    for (int a = 0; a < 3; a++) {
        for (int b = 0; b < 3; b++) {
            int ia = i0 + a;
            int jb = j0 + b;
            float acc = p3[a][b];
            if (jb > ia) acc -= 3.402823466e+38f;
            if (jb <= ia) acc += se[ia][47 - ia + jb];
            Z[base + ia * 48 + jb] = acc;
        }
    }
}

__global__ __launch_bounds__(256) void col_max_k(const float* Z, float* cmax)
{
    int c = blockIdx.x * 256 + threadIdx.x;
    const float* p = Z + c;
    float m = -3.402823466e+38f;
    for (int s = 0; s < 900; s++) m = fmaxf(m, p[(size_t)s * 18432]);
    cmax[c] = m;
}

__global__ __launch_bounds__(256) void col_expsum_k(float* Z, const float* cmax, float* csum)
{
    int c = blockIdx.x * 256 + threadIdx.x;
    float m = cmax[c];
    float* p = Z + c;
    float sum = 0.f;
    for (int s = 0; s < 900; s++) {
        float v = __expf(p[(size_t)s * 18432] - m);
        p[(size_t)s * 18432] = v;
        sum += v;
    }
    csum[c] = sum;
}

__global__ __launch_bounds__(256) void attn_out_k(
    const float* Z, const float* csum, const float* V, float* O, int vs)
{
    const int s = blockIdx.x;
    const int h = blockIdx.y;
    const int tid = threadIdx.x;
    __shared__ float sp[48][49];
    __shared__ float sv[48][33];
    size_t base = (size_t)s * 18432 + (size_t)h * 2304;
    for (int e = tid; e < 2304; e += 256) {
        int i = e / 48;
        int j = e - i * 48;
        sp[i][j] = Z[base + e] / csum[h * 2304 + e];
    }
    for (int e = tid; e < 1536; e += 256) {
        int j = e >> 5;
        int d = e & 31;
        sv[j][d] = V[(size_t)(s * 48 + j) * vs + h * 32 + d];
    }
    __syncthreads();
    const int i0 = (tid >> 4) * 3;
    const int d0 = (tid & 15) * 2;
    float acc[3][2];
    for (int a = 0; a < 3; a++) {
        acc[a][0] = 0.f;
        acc[a][1] = 0.f;
    }
    for (int j = 0; j < 48; j++) {
        float pv[3];
        float vv[2];
        for (int a = 0; a < 3; a++) pv[a] = sp[i0 + a][j];
        vv[0] = sv[j][d0];
        vv[1] = sv[j][d0 + 1];
        for (int a = 0; a < 3; a++) {
            acc[a][0] += pv[a] * vv[0];
            acc[a][1] += pv[a] * vv[1];
        }
    }
    for (int a = 0; a < 3; a++) {
        size_t off = (size_t)((s * 8 + h) * 48 + i0 + a) * 32 + d0;
        O[off] = acc[a][0];
        O[off + 1] = acc[a][1];
    }
}

__device__ __forceinline__ float block_sum256(float v, float* sbuf)
{
    for (int o = 16; o > 0; o >>= 1) v += __shfl_down_sync(0xffffffffu, v, o);
    int w = threadIdx.x >> 5;
    int l = threadIdx.x & 31;
    if (l == 0) sbuf[w] = v;
    __syncthreads();
    if (w == 0) {
        v = (l < 8) ? sbuf[l] : 0.f;
        for (int o = 4; o > 0; o >>= 1) v += __shfl_down_sync(0xffffffffu, v, o);
        if (l == 0) sbuf[0] = v;
    }
    __syncthreads();
    float r = sbuf[0];
    __syncthreads();
    return r;
}

__global__ __launch_bounds__(256) void add_ln_k(const float* A, const float* B, float* O, __half* H)
{
    __shared__ float sbuf[8];
    size_t base = (size_t)blockIdx.x * 256;
    float v = A[base + threadIdx.x] + B[base + threadIdx.x];
    float mean = block_sum256(v, sbuf) * (1.f / 256.f);
    float d = v - mean;
    float var = block_sum256(d * d, sbuf) * (1.f / 256.f);
    float r = d * rsqrtf(var + 1e-5f);
    O[base + threadIdx.x] = r;
    if (H) H[base + threadIdx.x] = __float2half(r);
}

__global__ __launch_bounds__(256) void outproj_k(const float* H, const float* w,
                                                 const float* b, float* y)
{
    int warp = (blockIdx.x * 256 + threadIdx.x) >> 5;
    int lane = threadIdx.x & 31;
    if (warp >= 43200) return;
    const float* row = H + (size_t)warp * 256;
    float s = 0.f;
    for (int k = lane; k < 256; k += 32) s += row[k] * w[k];
    for (int o = 16; o > 0; o >>= 1) s += __shfl_down_sync(0xffffffffu, s, o);
    if (lane == 0) y[warp] = s + b[0];
}

__global__ __launch_bounds__(256) void final_softmax_k(const float* y, float* out)
{
    int s = blockIdx.x * 256 + threadIdx.x;
    if (s >= 900) return;
    float m = -3.402823466e+38f;
    for (int b = 0; b < 48; b++) m = fmaxf(m, y[b * 900 + s]);
    float sum = 0.f;
    for (int b = 0; b < 48; b++) sum += __expf(y[b * 900 + s] - m);
    float inv = 1.f / sum;
    for (int b = 0; b < 48; b++) out[b * 900 + s] = __expf(y[b * 900 + s] - m) * inv;
}